// round 6
// baseline (speedup 1.0000x reference)
#include <cuda_runtime.h>
#include <cstdint>

// ---------------------------------------------------------------------------
// Scratch (device globals — no allocation allowed)
// ---------------------------------------------------------------------------
__device__ float g_h1[16*64*128*128];          // enc1 out / dec2 out (reused)
__device__ float g_h2[16*128*64*64];           // enc2 out / dec1 out (reused)
__device__ float g_h3[16*256*64*64];           // enc3 out
__device__ float g_z [16*256*64*64];           // enc4 out (z) / quantized NCHW (reused)
__device__ float g_resid[65536*256];
__device__ float g_qsum [65536*256];
__device__ double g_loss[4];
__device__ float g_cnorm[4*1024];
__device__ float g_w4p[64*16*8];               // dec_w4 repacked [ci][16][co(pad 8)]
__device__ float g_d3[16*64*256*256];          // dec3 out; ALSO the 65536x1024 D matrix

// ---------------------------------------------------------------------------
// tf32 helpers (approximate Phase-A path only; correctness never depends on it)
// ---------------------------------------------------------------------------
__device__ __forceinline__ uint32_t f2tf(float f) {
    uint32_t u;
    asm("cvt.rna.tf32.f32 %0, %1;" : "=r"(u) : "f"(f));
    return u;
}

__device__ __forceinline__ void split2(float x, uint32_t& h, uint32_t& l) {
    h = f2tf(x);
    l = f2tf(x - __uint_as_float(h));
}

__device__ __forceinline__ void mma_tf32(float* c, const uint32_t* a,
                                         uint32_t b0, uint32_t b1) {
    asm volatile(
        "mma.sync.aligned.m16n8k8.row.col.f32.tf32.tf32.f32 "
        "{%0,%1,%2,%3},{%4,%5,%6,%7},{%8,%9},{%0,%1,%2,%3};"
        : "+f"(c[0]), "+f"(c[1]), "+f"(c[2]), "+f"(c[3])
        : "r"(a[0]), "r"(a[1]), "r"(a[2]), "r"(a[3]), "r"(b0), "r"(b1));
}

static const int PLW = 128*33;   // one smem plane in words (stride 33: conflict-free)

// ---------------------------------------------------------------------------
// Phase A: approximate distance matrix on tensor cores (split2, 3 MMAs).
// D[m,n] = cn[n] - 2 * R[m,:].cb[n,:]   (approx)
// tile 128x128, 8 warps of 64x32, K=256. Dynamic smem: 4 planes = 67584 B.
// ---------------------------------------------------------------------------
__global__ __launch_bounds__(256)
void vq_gemm_approx(const float* __restrict__ R, const float* __restrict__ cb,
                    const float* __restrict__ cn, float* __restrict__ D)
{
    extern __shared__ uint32_t dyn[];
    uint32_t* sA1 = dyn;
    uint32_t* sA2 = dyn + PLW;
    uint32_t* sB1 = dyn + 2*PLW;
    uint32_t* sB2 = dyn + 3*PLW;

    const int tid  = threadIdx.x;
    const int lane = tid & 31;
    const int warp = tid >> 5;
    const int wm = warp & 1;        // 0..1  (rows)
    const int wn = warp >> 1;       // 0..3  (cols)
    const int m0 = blockIdx.x << 7;
    const int n0 = blockIdx.y << 7;

    float acc[4][4][4];
#pragma unroll
    for (int i = 0; i < 4; i++)
#pragma unroll
        for (int j = 0; j < 4; j++)
#pragma unroll
            for (int k = 0; k < 4; k++) acc[i][j][k] = 0.f;

    for (int k0 = 0; k0 < 256; k0 += 32) {
#pragma unroll
        for (int i = 0; i < 4; i++) {
            int idx4 = tid + i*256;            // 1024 float4 per matrix
            int m  = idx4 >> 3;
            int kq = idx4 & 7;
            int oa = m*33 + kq*4;
            float4 a = *(const float4*)(R  + (size_t)(m0 + m)*256 + k0 + kq*4);
            split2(a.x, sA1[oa+0], sA2[oa+0]);
            split2(a.y, sA1[oa+1], sA2[oa+1]);
            split2(a.z, sA1[oa+2], sA2[oa+2]);
            split2(a.w, sA1[oa+3], sA2[oa+3]);
            float4 b = *(const float4*)(cb + (size_t)(n0 + m)*256 + k0 + kq*4);
            split2(b.x, sB1[oa+0], sB2[oa+0]);
            split2(b.y, sB1[oa+1], sB2[oa+1]);
            split2(b.z, sB1[oa+2], sB2[oa+2]);
            split2(b.w, sB1[oa+3], sB2[oa+3]);
        }
        __syncthreads();

#pragma unroll
        for (int ks = 0; ks < 4; ks++) {
            const int kb = ks*8 + (lane & 3);
            uint32_t b1f[4][2], b2f[4][2];
#pragma unroll
            for (int fn = 0; fn < 4; fn++) {
                int n = wn*32 + fn*8 + (lane >> 2);
                b1f[fn][0] = sB1[n*33 + kb];  b1f[fn][1] = sB1[n*33 + kb + 4];
                b2f[fn][0] = sB2[n*33 + kb];  b2f[fn][1] = sB2[n*33 + kb + 4];
            }
#pragma unroll
            for (int fm = 0; fm < 4; fm++) {
                int r = wm*64 + fm*16 + (lane >> 2);
                uint32_t a1[4], a2[4];
                a1[0] = sA1[r*33 + kb];     a1[1] = sA1[(r+8)*33 + kb];
                a1[2] = sA1[r*33 + kb+4];   a1[3] = sA1[(r+8)*33 + kb+4];
                a2[0] = sA2[r*33 + kb];     a2[1] = sA2[(r+8)*33 + kb];
                a2[2] = sA2[r*33 + kb+4];   a2[3] = sA2[(r+8)*33 + kb+4];
#pragma unroll
                for (int fn = 0; fn < 4; fn++) {
                    mma_tf32(acc[fm][fn], a2, b1f[fn][0], b1f[fn][1]);
                    mma_tf32(acc[fm][fn], a1, b2f[fn][0], b2f[fn][1]);
                    mma_tf32(acc[fm][fn], a1, b1f[fn][0], b1f[fn][1]);
                }
            }
        }
        __syncthreads();
    }

    // epilogue: write D = cn - 2*acc
#pragma unroll
    for (int fn = 0; fn < 4; fn++) {
        int col = n0 + wn*32 + fn*8 + 2*(lane & 3);
        float cn0 = cn[col], cn1 = cn[col + 1];
#pragma unroll
        for (int fm = 0; fm < 4; fm++) {
#pragma unroll
            for (int h = 0; h < 2; h++) {
                int rg = m0 + wm*64 + fm*16 + (lane >> 2) + h*8;
                float2 v;
                v.x = cn0 - 2.f*acc[fm][fn][h*2 + 0];
                v.y = cn1 - 2.f*acc[fm][fn][h*2 + 1];
                *(float2*)(D + (size_t)rg*1024 + col) = v;
            }
        }
    }
}

// ---------------------------------------------------------------------------
// Phase B: one warp per token. Scan approx row, exact-FFMA rescore of all
// candidates within EPS of approx min, lowest-index tie-break, then fused
// vq_update (loss, qsum+=, resid-=, index write).
// ---------------------------------------------------------------------------
__global__ __launch_bounds__(256)
void vq_select_update(const float* __restrict__ D, const float* __restrict__ cb,
                      const float* __restrict__ cn,
                      float* __restrict__ resid, float* __restrict__ qsum,
                      float* __restrict__ idx_out, int stage,
                      double* __restrict__ lossAcc)
{
    __shared__ double sLoss[8];
    const int warp = threadIdx.x >> 5;
    const int lane = threadIdx.x & 31;
    const int t = blockIdx.x*8 + warp;

    const float* drow = D + (size_t)t*1024;

    // pass 1: approx min over the row
    float mn = 3.402823466e38f;
#pragma unroll
    for (int j0 = 0; j0 < 1024; j0 += 32)
        mn = fminf(mn, drow[j0 + lane]);
#pragma unroll
    for (int o = 16; o; o >>= 1)
        mn = fminf(mn, __shfl_xor_sync(0xffffffffu, mn, o));
    const float thr = mn + 0.02f;

    // residual row in registers (8 floats per lane)
    float4 r0 = *(const float4*)(resid + (size_t)t*256 + lane*8);
    float4 r1 = *(const float4*)(resid + (size_t)t*256 + lane*8 + 4);

    float bestd = 3.402823466e38f;
    int   bestn = 0;
    for (int j0 = 0; j0 < 1024; j0 += 32) {
        float dv = drow[j0 + lane];
        unsigned m = __ballot_sync(0xffffffffu, dv <= thr);
        while (m) {
            int src = __ffs(m) - 1; m &= m - 1;
            int j = j0 + src;
            const float* c = cb + (size_t)j*256;
            float4 c0 = *(const float4*)(c + lane*8);
            float4 c1 = *(const float4*)(c + lane*8 + 4);
            float dot = r0.x*c0.x + r0.y*c0.y + r0.z*c0.z + r0.w*c0.w
                      + r1.x*c1.x + r1.y*c1.y + r1.z*c1.z + r1.w*c1.w;
#pragma unroll
            for (int o = 16; o; o >>= 1)
                dot += __shfl_xor_sync(0xffffffffu, dot, o);
            float de = cn[j] - 2.f*dot;
            if (de < bestd) { bestd = de; bestn = j; }  // j ascending: ties -> lowest
        }
    }

    // fused update
    const float* q = cb + (size_t)bestn*256;
    float4 q0 = *(const float4*)(q + lane*8);
    float4 q1 = *(const float4*)(q + lane*8 + 4);
    float4 s0 = *(float4*)(qsum + (size_t)t*256 + lane*8);
    float4 s1 = *(float4*)(qsum + (size_t)t*256 + lane*8 + 4);

    float ls = 0.f;
    {
        float d;
        d = q0.x-r0.x; ls += d*d;  d = q0.y-r0.y; ls += d*d;
        d = q0.z-r0.z; ls += d*d;  d = q0.w-r0.w; ls += d*d;
        d = q1.x-r1.x; ls += d*d;  d = q1.y-r1.y; ls += d*d;
        d = q1.z-r1.z; ls += d*d;  d = q1.w-r1.w; ls += d*d;
    }
    s0.x += q0.x; s0.y += q0.y; s0.z += q0.z; s0.w += q0.w;
    s1.x += q1.x; s1.y += q1.y; s1.z += q1.z; s1.w += q1.w;
    r0.x -= q0.x; r0.y -= q0.y; r0.z -= q0.z; r0.w -= q0.w;
    r1.x -= q1.x; r1.y -= q1.y; r1.z -= q1.z; r1.w -= q1.w;
    *(float4*)(qsum  + (size_t)t*256 + lane*8)     = s0;
    *(float4*)(qsum  + (size_t)t*256 + lane*8 + 4) = s1;
    *(float4*)(resid + (size_t)t*256 + lane*8)     = r0;
    *(float4*)(resid + (size_t)t*256 + lane*8 + 4) = r1;

#pragma unroll
    for (int o = 16; o; o >>= 1) ls += __shfl_down_sync(0xffffffffu, ls, o);
    if (lane == 0) {
        sLoss[warp] = (double)ls;
        idx_out[(t >> 12)*16384 + stage*4096 + (t & 4095)] = (float)bestn;
    }
    __syncthreads();
    if (threadIdx.x == 0) {
        double tot = 0.0;
#pragma unroll
        for (int w = 0; w < 8; w++) tot += sLoss[w];
        atomicAdd(lossAcc + stage, tot);
    }
}

// ---------------------------------------------------------------------------
// Direct conv, NCHW (FFMA — known-exact path).
// Block: 128 thr = 16 px-cols x 8 cout-groups. Thread: 4 px x 8 couts.
// ---------------------------------------------------------------------------
template<int K, int S, int CIN_T>
__global__ __launch_bounds__(128)
void conv2d_tiled(const float* __restrict__ in, const float* __restrict__ w,
                  const float* __restrict__ bias, float* __restrict__ out,
                  int Cin, int H, int W, int Cout, int Ho, int Wo,
                  int pad, int relu)
{
    constexpr int IH = 3*S + K;
    constexpr int IW = 15*S + K;
    constexpr int KK = K*K;
    __shared__ __align__(16) float s_in[CIN_T*IH*IW];
    __shared__ __align__(16) float s_w [CIN_T*KK*64];

    const int tid = threadIdx.x;
    const int px  = tid & 15;
    const int cg  = tid >> 4;
    const int hb  = Ho >> 2;
    const int b   = blockIdx.y / hb;
    const int oy0 = (blockIdx.y % hb) * 4;
    const int ox0 = blockIdx.x * 16;
    const int co0 = blockIdx.z * 64;
    const int iy0 = oy0*S - pad;
    const int ix0 = ox0*S - pad;

    float acc[4][8];
#pragma unroll
    for (int p = 0; p < 4; p++)
#pragma unroll
        for (int c = 0; c < 8; c++) acc[p][c] = 0.f;

    for (int ci0 = 0; ci0 < Cin; ci0 += CIN_T) {
        for (int idx = tid; idx < CIN_T*IH*IW; idx += 128) {
            int ci  = idx / (IH*IW);
            int rem = idx % (IH*IW);
            int r   = rem / IW, c = rem % IW;
            int iy  = iy0 + r, ix = ix0 + c;
            float v = 0.f;
            if ((unsigned)iy < (unsigned)H && (unsigned)ix < (unsigned)W &&
                (ci0 + ci) < Cin)
                v = in[((b*Cin + ci0 + ci)*H + iy)*W + ix];
            s_in[idx] = v;
        }
        for (int idx = tid; idx < CIN_T*KK*64; idx += 128) {
            int co  = idx & 63;
            int rem = idx >> 6;
            int kk  = rem % KK;
            int ci  = rem / KK;
            float v = 0.f;
            if ((ci0 + ci) < Cin)
                v = w[((co0 + co)*Cin + ci0 + ci)*KK + kk];
            s_w[idx] = v;
        }
        __syncthreads();

        for (int ci = 0; ci < CIN_T; ci++) {
#pragma unroll
            for (int kh = 0; kh < K; kh++) {
#pragma unroll
                for (int kw = 0; kw < K; kw++) {
                    const float4* wp =
                        (const float4*)(s_w + ((ci*KK + kh*K + kw) << 6) + (cg << 3));
                    float4 w0 = wp[0], w1 = wp[1];
#pragma unroll
                    for (int p = 0; p < 4; p++) {
                        float iv = s_in[(ci*IH + p*S + kh)*IW + px*S + kw];
                        acc[p][0] += iv*w0.x; acc[p][1] += iv*w0.y;
                        acc[p][2] += iv*w0.z; acc[p][3] += iv*w0.w;
                        acc[p][4] += iv*w1.x; acc[p][5] += iv*w1.y;
                        acc[p][6] += iv*w1.z; acc[p][7] += iv*w1.w;
                    }
                }
            }
        }
        __syncthreads();
    }

#pragma unroll
    for (int c = 0; c < 8; c++) {
        int co = co0 + (cg << 3) + c;
        float bv = bias[co];
#pragma unroll
        for (int p = 0; p < 4; p++) {
            float v = acc[p][c] + bv;
            if (relu) v = fmaxf(v, 0.f);
            out[((b*Cout + co)*Ho + oy0 + p)*Wo + ox0 + px] = v;
        }
    }
}

// ---------------------------------------------------------------------------
// ConvTranspose2d, k=4, s=2, p=1 via parity-tap decomposition (FFMA path).
// ---------------------------------------------------------------------------
template<int COG, int PXW, bool PACKED>
__global__ __launch_bounds__(COG*PXW)
void convT_tiled(const float* __restrict__ in, const float* __restrict__ w,
                 const float* __restrict__ bias, float* __restrict__ out,
                 int Cin, int Hin, int Win, int CoutW, int CoutReal, int act)
{
    constexpr int CIN_T = 8;
    constexpr int IH = 4;
    constexpr int IW = PXW/2 + 2;
    constexpr int NCO = COG*8;
    __shared__ __align__(16) float s_in[CIN_T*IH*IW];
    __shared__ __align__(16) float s_w [CIN_T*16*NCO];

    const int tid = threadIdx.x;
    const int px  = tid % PXW;
    const int cg  = tid / PXW;
    const int Ho = Hin*2, Wo = Win*2;
    const int hb  = Ho >> 2;
    const int b   = blockIdx.y / hb;
    const int oy0 = (blockIdx.y % hb) * 4;
    const int ox0 = blockIdx.x * PXW;
    const int co0 = blockIdx.z * NCO;
    const int m0  = oy0 >> 1;
    const int mx0 = ox0 >> 1;

    const int ox = ox0 + px;
    const int ex = ox & 1;
    const int mx = ox >> 1;
    int kxt[2], cxt[2];
    if (ex == 0) { kxt[0]=1; cxt[0]=mx-mx0+1; kxt[1]=3; cxt[1]=mx-mx0;   }
    else         { kxt[0]=0; cxt[0]=mx-mx0+2; kxt[1]=2; cxt[1]=mx-mx0+1; }

    float acc[4][8];
#pragma unroll
    for (int p = 0; p < 4; p++)
#pragma unroll
        for (int c = 0; c < 8; c++) acc[p][c] = 0.f;

    for (int ci0 = 0; ci0 < Cin; ci0 += CIN_T) {
        for (int idx = tid; idx < CIN_T*IH*IW; idx += COG*PXW) {
            int ci  = idx / (IH*IW);
            int rem = idx % (IH*IW);
            int r = rem / IW, c = rem % IW;
            int iy = m0 - 1 + r, ix = mx0 - 1 + c;
            float v = 0.f;
            if ((unsigned)iy < (unsigned)Hin && (unsigned)ix < (unsigned)Win)
                v = in[((b*Cin + ci0 + ci)*Hin + iy)*Win + ix];
            s_in[idx] = v;
        }
        for (int idx = tid; idx < CIN_T*16*NCO; idx += COG*PXW) {
            int co  = idx % NCO;
            int rem = idx / NCO;
            int kk  = rem % 16;
            int ci  = rem / 16;
            float v;
            if (PACKED) v = w[((ci0 + ci)*16 + kk)*8 + co];
            else        v = w[((ci0 + ci)*CoutW + co0 + co)*16 + kk];
            s_w[idx] = v;
        }
        __syncthreads();

        for (int ci = 0; ci < CIN_T; ci++) {
#pragma unroll
            for (int ey = 0; ey < 2; ey++) {
#pragma unroll
                for (int jy = 0; jy < 2; jy++) {
                    const int ky    = (ey==0) ? (jy==0 ? 1 : 3) : (jy==0 ? 0 : 2);
                    const int rbase = (ey==0) ? (jy==0 ? 1 : 0) : (jy==0 ? 2 : 1);
#pragma unroll
                    for (int jx = 0; jx < 2; jx++) {
                        int kk = ky*4 + kxt[jx];
                        const float4* wp =
                            (const float4*)(s_w + (ci*16 + kk)*NCO + cg*8);
                        float4 w0 = wp[0], w1 = wp[1];
#pragma unroll
                        for (int ph = 0; ph < 2; ph++) {
                            int p   = ey + ph*2;
                            int row = ph + rbase;
                            float iv = s_in[(ci*IH + row)*IW + cxt[jx]];
                            acc[p][0] += iv*w0.x; acc[p][1] += iv*w0.y;
                            acc[p][2] += iv*w0.z; acc[p][3] += iv*w0.w;
                            acc[p][4] += iv*w1.x; acc[p][5] += iv*w1.y;
                            acc[p][6] += iv*w1.z; acc[p][7] += iv*w1.w;
                        }
                    }
                }
            }
        }
        __syncthreads();
    }

#pragma unroll
    for (int c = 0; c < 8; c++) {
        int co = co0 + cg*8 + c;
        if (co >= CoutReal) continue;
        float bv = bias[co];
#pragma unroll
        for (int p = 0; p < 4; p++) {
            float v = acc[p][c] + bv;
            v = act ? tanhf(v) : fmaxf(v, 0.f);
            out[((b*CoutReal + co)*Ho + oy0 + p)*Wo + ox] = v;
        }
    }
}

// ---------------------------------------------------------------------------
// Helpers
// ---------------------------------------------------------------------------
__global__ void cnorm_kernel(const float* __restrict__ cb, float* __restrict__ cn) {
    int row  = (blockIdx.x*blockDim.x + threadIdx.x) >> 5;
    int lane = threadIdx.x & 31;
    if (row >= 4096) return;
    const float* p = cb + (size_t)row*256;
    float s = 0.f;
    for (int c = lane; c < 256; c += 32) { float v = p[c]; s += v*v; }
#pragma unroll
    for (int o = 16; o; o >>= 1) s += __shfl_down_sync(0xffffffffu, s, o);
    if (!lane) cn[row] = s;
}

__global__ void repack_w4(const float* __restrict__ w, float* __restrict__ wp) {
    int idx = blockIdx.x*256 + threadIdx.x;
    if (idx >= 64*16*8) return;
    int co = idx & 7, rem = idx >> 3;
    int kk = rem & 15, ci = rem >> 4;
    wp[idx] = (co < 3) ? w[(ci*3 + co)*16 + kk] : 0.f;
}

__global__ void zero_loss(double* l) { if (threadIdx.x < 4) l[threadIdx.x] = 0.0; }

__global__ void write_loss(const double* __restrict__ l, float* __restrict__ o) {
    if (threadIdx.x < 4)
        o[threadIdx.x] = (float)(l[threadIdx.x] * (1.0/(65536.0*256.0)));
}

// z (16,256,4096) NCHW -> tokens (65536,256); zero qsum
__global__ void z_to_tokens(const float* __restrict__ z,
                            float* __restrict__ resid, float* __restrict__ qsum)
{
    __shared__ float t[32][33];
    int b  = blockIdx.z;
    int s0 = blockIdx.x*32;
    int c0 = blockIdx.y*32;
    int x  = threadIdx.x;
    for (int y = threadIdx.y; y < 32; y += 8)
        t[y][x] = z[((size_t)b*256 + c0 + y)*4096 + s0 + x];
    __syncthreads();
    for (int y = threadIdx.y; y < 32; y += 8) {
        size_t o = ((size_t)b*4096 + s0 + y)*256 + c0 + x;
        resid[o] = t[x][y];
        qsum[o]  = 0.f;
    }
}

// tokens -> NCHW (two destinations: dec1 input + quantized output)
__global__ void tokens_to_z(const float* __restrict__ qsum,
                            float* __restrict__ z1, float* __restrict__ z2)
{
    __shared__ float t[32][33];
    int b  = blockIdx.z;
    int c0 = blockIdx.x*32;
    int s0 = blockIdx.y*32;
    int x  = threadIdx.x;
    for (int y = threadIdx.y; y < 32; y += 8)
        t[y][x] = qsum[((size_t)b*4096 + s0 + y)*256 + c0 + x];
    __syncthreads();
    for (int y = threadIdx.y; y < 32; y += 8) {
        float v = t[x][y];
        size_t o = ((size_t)b*256 + c0 + y)*4096 + s0 + x;
        z1[o] = v; z2[o] = v;
    }
}

// ---------------------------------------------------------------------------
// Launch
// ---------------------------------------------------------------------------
extern "C" void kernel_launch(void* const* d_in, const int* in_sizes, int n_in,
                              void* d_out, int out_size)
{
    const float* x   = (const float*)d_in[0];
    const float* ew1 = (const float*)d_in[1];  const float* eb1 = (const float*)d_in[2];
    const float* ew2 = (const float*)d_in[3];  const float* eb2 = (const float*)d_in[4];
    const float* ew3 = (const float*)d_in[5];  const float* eb3 = (const float*)d_in[6];
    const float* ew4 = (const float*)d_in[7];  const float* eb4 = (const float*)d_in[8];
    const float* cbs = (const float*)d_in[9];
    const float* dw1 = (const float*)d_in[10]; const float* db1 = (const float*)d_in[11];
    const float* dw2 = (const float*)d_in[12]; const float* db2 = (const float*)d_in[13];
    const float* dw3 = (const float*)d_in[14]; const float* db3 = (const float*)d_in[15];
    const float* dw4 = (const float*)d_in[16]; const float* db4 = (const float*)d_in[17];
    float* out = (float*)d_out;

    float *h1, *h2, *h3, *z, *resid, *qsum, *cnorm, *w4p, *d3;
    double* loss;
    cudaGetSymbolAddress((void**)&h1,   g_h1);
    cudaGetSymbolAddress((void**)&h2,   g_h2);
    cudaGetSymbolAddress((void**)&h3,   g_h3);
    cudaGetSymbolAddress((void**)&z,    g_z);
    cudaGetSymbolAddress((void**)&resid,g_resid);
    cudaGetSymbolAddress((void**)&qsum, g_qsum);
    cudaGetSymbolAddress((void**)&loss, g_loss);
    cudaGetSymbolAddress((void**)&cnorm,g_cnorm);
    cudaGetSymbolAddress((void**)&w4p,  g_w4p);
    cudaGetSymbolAddress((void**)&d3,   g_d3);

    // output layout: recon | indices | commit_loss | quantized
    float* recO   = out;
    float* idxO   = out + 12582912;                 // 16*3*512*512
    float* lossO  = idxO + 262144;                  // 16*4*64*64
    float* quantO = lossO + 4;

    // dynamic smem opt-in for Phase A (4 planes of 128*33 words)
    const int PA_SMEM = 4*PLW*4;                    // 67584
    cudaFuncSetAttribute(vq_gemm_approx, cudaFuncAttributeMaxDynamicSharedMemorySize, PA_SMEM);

    // prep
    repack_w4   <<<32, 256>>>(dw4, w4p);
    cnorm_kernel<<<512, 256>>>(cbs, cnorm);
    zero_loss   <<<1, 32>>>(loss);

    // ---- encoder (FFMA, exact) ----
    conv2d_tiled<4,2,4><<<dim3(8, 32*16, 1), 128>>>(x,  ew1, eb1, h1,   3, 256, 256,  64, 128, 128, 1, 1);
    conv2d_tiled<4,2,8><<<dim3(4, 16*16, 2), 128>>>(h1, ew2, eb2, h2,  64, 128, 128, 128,  64,  64, 1, 1);
    conv2d_tiled<3,1,8><<<dim3(4, 16*16, 4), 128>>>(h2, ew3, eb3, h3, 128,  64,  64, 256,  64,  64, 1, 1);
    conv2d_tiled<3,1,8><<<dim3(4, 16*16, 4), 128>>>(h3, ew4, eb4, z,  256,  64,  64, 256,  64,  64, 1, 0);

    // ---- residual VQ: TC approx distances + exact FFMA rescore ----
    z_to_tokens<<<dim3(128, 8, 16), dim3(32, 8)>>>(z, resid, qsum);
    for (int s = 0; s < 4; s++) {
        vq_gemm_approx  <<<dim3(512, 8), 256, PA_SMEM>>>(resid, cbs + (size_t)s*1024*256,
                                                         cnorm + s*1024, d3);
        vq_select_update<<<8192, 256>>>(d3, cbs + (size_t)s*1024*256, cnorm + s*1024,
                                        resid, qsum, idxO, s, loss);
    }
    write_loss <<<1, 32>>>(loss, lossO);
    tokens_to_z<<<dim3(8, 128, 16), dim3(32, 8)>>>(qsum, z, quantO);

    // ---- decoder (FFMA, exact) ----
    conv2d_tiled<3,1,8><<<dim3(4, 16*16, 2), 128>>>(z, dw1, db1, h2, 256, 64, 64, 128, 64, 64, 1, 1);
    convT_tiled<8,  16, false><<<dim3( 8,  32*16, 1), 128>>>(h2, dw2, db2, h1, 128,  64,  64, 64, 64, 0);
    convT_tiled<8,  16, false><<<dim3(16,  64*16, 1), 128>>>(h1, dw3, db3, d3,  64, 128, 128, 64, 64, 0);
    convT_tiled<1, 128, true ><<<dim3( 4, 128*16, 1), 128>>>(d3, w4p, db4, recO, 64, 256, 256,  8,  3, 1);
}

// round 7
// speedup vs baseline: 1.0845x; 1.0845x over previous
#include <cuda_runtime.h>
#include <cstdint>

// ---------------------------------------------------------------------------
// Scratch (device globals — no allocation allowed)
// ---------------------------------------------------------------------------
__device__ float g_h1[16*64*128*128];          // enc1 out / dec2 out (reused)
__device__ float g_h2[16*128*64*64];           // enc2 out / dec1 out (reused)
__device__ float g_h3[16*256*64*64];           // enc3 out
__device__ float g_z [16*256*64*64];           // enc4 out (z) / quantized NCHW (reused)
__device__ float g_resid[65536*256];
__device__ float g_qsum [65536*256];
__device__ double g_loss[4];
__device__ float g_cnorm[4*1024];
__device__ unsigned g_rowmin[65536];
__device__ float g_w4p[64*16*8];               // dec_w4 repacked [ci][16][co(pad 8)]
__device__ float g_d3[16*64*256*256];          // dec3 out; ALSO the 65536x1024 D matrix

// ---------------------------------------------------------------------------
// tf32 helpers (approximate Phase-A path only; correctness never depends on it)
// ---------------------------------------------------------------------------
__device__ __forceinline__ uint32_t f2tf(float f) {
    uint32_t u;
    asm("cvt.rna.tf32.f32 %0, %1;" : "=r"(u) : "f"(f));
    return u;
}

__device__ __forceinline__ void mma_tf32(float* c, const uint32_t* a,
                                         uint32_t b0, uint32_t b1) {
    asm volatile(
        "mma.sync.aligned.m16n8k8.row.col.f32.tf32.tf32.f32 "
        "{%0,%1,%2,%3},{%4,%5,%6,%7},{%8,%9},{%0,%1,%2,%3};"
        : "+f"(c[0]), "+f"(c[1]), "+f"(c[2]), "+f"(c[3])
        : "r"(a[0]), "r"(a[1]), "r"(a[2]), "r"(a[3]), "r"(b0), "r"(b1));
}

// order-preserving float <-> uint32 (for atomicMin)
__device__ __forceinline__ unsigned fenc(float d) {
    unsigned u = __float_as_uint(d);
    return (u & 0x80000000u) ? ~u : (u | 0x80000000u);
}
__device__ __forceinline__ float fdec(unsigned e) {
    unsigned u = (e & 0x80000000u) ? (e & 0x7FFFFFFFu) : ~e;
    return __uint_as_float(u);
}

static const int PLW = 128*33;   // one smem plane in words (stride 33: conflict-free)

// ---------------------------------------------------------------------------
// Phase A: approximate distance matrix, single tf32 MMA (err ~5e-4 << 0.02).
// D[m,n] = cn[n] - 2 * R[m,:].cb[n,:]; also per-row min -> rowmin (atomicMin).
// tile 128x128, 8 warps of 64x32, K=256. Dynamic smem: 2 planes + 512 B.
// ---------------------------------------------------------------------------
__global__ __launch_bounds__(256)
void vq_gemm_approx(const float* __restrict__ R, const float* __restrict__ cb,
                    const float* __restrict__ cn, float* __restrict__ D,
                    unsigned* __restrict__ rowmin)
{
    extern __shared__ uint32_t dyn[];
    uint32_t* sA = dyn;
    uint32_t* sB = dyn + PLW;
    unsigned* sMin = (unsigned*)(dyn + 2*PLW);

    const int tid  = threadIdx.x;
    const int lane = tid & 31;
    const int warp = tid >> 5;
    const int wm = warp & 1;        // 0..1  (rows)
    const int wn = warp >> 1;       // 0..3  (cols)
    const int m0 = blockIdx.x << 7;
    const int n0 = blockIdx.y << 7;

    float acc[4][4][4];
#pragma unroll
    for (int i = 0; i < 4; i++)
#pragma unroll
        for (int j = 0; j < 4; j++)
#pragma unroll
            for (int k = 0; k < 4; k++) acc[i][j][k] = 0.f;

    if (tid < 128) sMin[tid] = 0xFFFFFFFFu;

    for (int k0 = 0; k0 < 256; k0 += 32) {
#pragma unroll
        for (int i = 0; i < 4; i++) {
            int idx4 = tid + i*256;            // 1024 float4 per matrix
            int m  = idx4 >> 3;
            int kq = idx4 & 7;
            int oa = m*33 + kq*4;
            float4 a = *(const float4*)(R  + (size_t)(m0 + m)*256 + k0 + kq*4);
            sA[oa+0] = f2tf(a.x); sA[oa+1] = f2tf(a.y);
            sA[oa+2] = f2tf(a.z); sA[oa+3] = f2tf(a.w);
            float4 b = *(const float4*)(cb + (size_t)(n0 + m)*256 + k0 + kq*4);
            sB[oa+0] = f2tf(b.x); sB[oa+1] = f2tf(b.y);
            sB[oa+2] = f2tf(b.z); sB[oa+3] = f2tf(b.w);
        }
        __syncthreads();

#pragma unroll
        for (int ks = 0; ks < 4; ks++) {
            const int kb = ks*8 + (lane & 3);
            uint32_t bf[4][2];
#pragma unroll
            for (int fn = 0; fn < 4; fn++) {
                int n = wn*32 + fn*8 + (lane >> 2);
                bf[fn][0] = sB[n*33 + kb];  bf[fn][1] = sB[n*33 + kb + 4];
            }
#pragma unroll
            for (int fm = 0; fm < 4; fm++) {
                int r = wm*64 + fm*16 + (lane >> 2);
                uint32_t af[4];
                af[0] = sA[r*33 + kb];     af[1] = sA[(r+8)*33 + kb];
                af[2] = sA[r*33 + kb+4];   af[3] = sA[(r+8)*33 + kb+4];
#pragma unroll
                for (int fn = 0; fn < 4; fn++)
                    mma_tf32(acc[fm][fn], af, bf[fn][0], bf[fn][1]);
            }
        }
        __syncthreads();
    }

    // epilogue: D = cn - 2*acc, plus per-row min
    float cnv[4][2];
#pragma unroll
    for (int fn = 0; fn < 4; fn++) {
        int col = n0 + wn*32 + fn*8 + 2*(lane & 3);
        cnv[fn][0] = cn[col];
        cnv[fn][1] = cn[col + 1];
    }
#pragma unroll
    for (int fm = 0; fm < 4; fm++) {
#pragma unroll
        for (int h = 0; h < 2; h++) {
            int rl = wm*64 + fm*16 + (lane >> 2) + h*8;
            int rg = m0 + rl;
            float mn = 3.402823466e38f;
#pragma unroll
            for (int fn = 0; fn < 4; fn++) {
                int col = n0 + wn*32 + fn*8 + 2*(lane & 3);
                float2 v;
                v.x = cnv[fn][0] - 2.f*acc[fm][fn][h*2 + 0];
                v.y = cnv[fn][1] - 2.f*acc[fm][fn][h*2 + 1];
                mn = fminf(mn, fminf(v.x, v.y));
                *(float2*)(D + (size_t)rg*1024 + col) = v;
            }
            atomicMin(&sMin[rl], fenc(mn));
        }
    }
    __syncthreads();
    if (tid < 128) atomicMin(&rowmin[m0 + tid], sMin[tid]);
}

__global__ void init_rowmin(unsigned* rowmin) {
    rowmin[blockIdx.x*1024 + threadIdx.x] = 0xFFFFFFFFu;
}

// ---------------------------------------------------------------------------
// Phase B: one warp per token. thr = rowmin + EPS; single scan of the row,
// exact-FFMA rescore of candidates, lowest-index tie-break, fused vq_update.
// ---------------------------------------------------------------------------
__global__ __launch_bounds__(256)
void vq_select_update(const float* __restrict__ D, const float* __restrict__ cb,
                      const float* __restrict__ cn,
                      const unsigned* __restrict__ rowmin,
                      float* __restrict__ resid, float* __restrict__ qsum,
                      float* __restrict__ idx_out, int stage,
                      double* __restrict__ lossAcc)
{
    __shared__ double sLoss[8];
    const int warp = threadIdx.x >> 5;
    const int lane = threadIdx.x & 31;
    const int t = blockIdx.x*8 + warp;

    const float* drow = D + (size_t)t*1024;
    const float thr = fdec(rowmin[t]) + 0.02f;

    // residual row in registers (8 floats per lane)
    float4 r0 = *(const float4*)(resid + (size_t)t*256 + lane*8);
    float4 r1 = *(const float4*)(resid + (size_t)t*256 + lane*8 + 4);

    float bestd = 3.402823466e38f;
    int   bestn = 0;
    for (int j0 = 0; j0 < 1024; j0 += 32) {
        float dv = drow[j0 + lane];
        unsigned m = __ballot_sync(0xffffffffu, dv <= thr);
        while (m) {
            int src = __ffs(m) - 1; m &= m - 1;
            int j = j0 + src;
            const float* c = cb + (size_t)j*256;
            float4 c0 = *(const float4*)(c + lane*8);
            float4 c1 = *(const float4*)(c + lane*8 + 4);
            float dot = r0.x*c0.x + r0.y*c0.y + r0.z*c0.z + r0.w*c0.w
                      + r1.x*c1.x + r1.y*c1.y + r1.z*c1.z + r1.w*c1.w;
#pragma unroll
            for (int o = 16; o; o >>= 1)
                dot += __shfl_xor_sync(0xffffffffu, dot, o);
            float de = cn[j] - 2.f*dot;
            if (de < bestd) { bestd = de; bestn = j; }  // j ascending: ties -> lowest
        }
    }

    // fused update
    const float* q = cb + (size_t)bestn*256;
    float4 q0 = *(const float4*)(q + lane*8);
    float4 q1 = *(const float4*)(q + lane*8 + 4);
    float4 s0 = *(float4*)(qsum + (size_t)t*256 + lane*8);
    float4 s1 = *(float4*)(qsum + (size_t)t*256 + lane*8 + 4);

    float ls = 0.f;
    {
        float d;
        d = q0.x-r0.x; ls += d*d;  d = q0.y-r0.y; ls += d*d;
        d = q0.z-r0.z; ls += d*d;  d = q0.w-r0.w; ls += d*d;
        d = q1.x-r1.x; ls += d*d;  d = q1.y-r1.y; ls += d*d;
        d = q1.z-r1.z; ls += d*d;  d = q1.w-r1.w; ls += d*d;
    }
    s0.x += q0.x; s0.y += q0.y; s0.z += q0.z; s0.w += q0.w;
    s1.x += q1.x; s1.y += q1.y; s1.z += q1.z; s1.w += q1.w;
    r0.x -= q0.x; r0.y -= q0.y; r0.z -= q0.z; r0.w -= q0.w;
    r1.x -= q1.x; r1.y -= q1.y; r1.z -= q1.z; r1.w -= q1.w;
    *(float4*)(qsum  + (size_t)t*256 + lane*8)     = s0;
    *(float4*)(qsum  + (size_t)t*256 + lane*8 + 4) = s1;
    *(float4*)(resid + (size_t)t*256 + lane*8)     = r0;
    *(float4*)(resid + (size_t)t*256 + lane*8 + 4) = r1;

#pragma unroll
    for (int o = 16; o; o >>= 1) ls += __shfl_down_sync(0xffffffffu, ls, o);
    if (lane == 0) {
        sLoss[warp] = (double)ls;
        idx_out[(t >> 12)*16384 + stage*4096 + (t & 4095)] = (float)bestn;
    }
    __syncthreads();
    if (threadIdx.x == 0) {
        double tot = 0.0;
#pragma unroll
        for (int w = 0; w < 8; w++) tot += sLoss[w];
        atomicAdd(lossAcc + stage, tot);
    }
}

// ---------------------------------------------------------------------------
// Direct conv, NCHW (FFMA — known-exact path).
// Block: 128 thr = 16 px-cols x 8 cout-groups. Thread: 4 px x 8 couts.
// ---------------------------------------------------------------------------
template<int K, int S, int CIN_T>
__global__ __launch_bounds__(128)
void conv2d_tiled(const float* __restrict__ in, const float* __restrict__ w,
                  const float* __restrict__ bias, float* __restrict__ out,
                  int Cin, int H, int W, int Cout, int Ho, int Wo,
                  int pad, int relu)
{
    constexpr int IH = 3*S + K;
    constexpr int IW = 15*S + K;
    constexpr int KK = K*K;
    __shared__ __align__(16) float s_in[CIN_T*IH*IW];
    __shared__ __align__(16) float s_w [CIN_T*KK*64];

    const int tid = threadIdx.x;
    const int px  = tid & 15;
    const int cg  = tid >> 4;
    const int hb  = Ho >> 2;
    const int b   = blockIdx.y / hb;
    const int oy0 = (blockIdx.y % hb) * 4;
    const int ox0 = blockIdx.x * 16;
    const int co0 = blockIdx.z * 64;
    const int iy0 = oy0*S - pad;
    const int ix0 = ox0*S - pad;

    float acc[4][8];
#pragma unroll
    for (int p = 0; p < 4; p++)
#pragma unroll
        for (int c = 0; c < 8; c++) acc[p][c] = 0.f;

    for (int ci0 = 0; ci0 < Cin; ci0 += CIN_T) {
        for (int idx = tid; idx < CIN_T*IH*IW; idx += 128) {
            int ci  = idx / (IH*IW);
            int rem = idx % (IH*IW);
            int r   = rem / IW, c = rem % IW;
            int iy  = iy0 + r, ix = ix0 + c;
            float v = 0.f;
            if ((unsigned)iy < (unsigned)H && (unsigned)ix < (unsigned)W &&
                (ci0 + ci) < Cin)
                v = in[((b*Cin + ci0 + ci)*H + iy)*W + ix];
            s_in[idx] = v;
        }
        for (int idx = tid; idx < CIN_T*KK*64; idx += 128) {
            int co  = idx & 63;
            int rem = idx >> 6;
            int kk  = rem % KK;
            int ci  = rem / KK;
            float v = 0.f;
            if ((ci0 + ci) < Cin)
                v = w[((co0 + co)*Cin + ci0 + ci)*KK + kk];
            s_w[idx] = v;
        }
        __syncthreads();

        for (int ci = 0; ci < CIN_T; ci++) {
#pragma unroll
            for (int kh = 0; kh < K; kh++) {
#pragma unroll
                for (int kw = 0; kw < K; kw++) {
                    const float4* wp =
                        (const float4*)(s_w + ((ci*KK + kh*K + kw) << 6) + (cg << 3));
                    float4 w0 = wp[0], w1 = wp[1];
#pragma unroll
                    for (int p = 0; p < 4; p++) {
                        float iv = s_in[(ci*IH + p*S + kh)*IW + px*S + kw];
                        acc[p][0] += iv*w0.x; acc[p][1] += iv*w0.y;
                        acc[p][2] += iv*w0.z; acc[p][3] += iv*w0.w;
                        acc[p][4] += iv*w1.x; acc[p][5] += iv*w1.y;
                        acc[p][6] += iv*w1.z; acc[p][7] += iv*w1.w;
                    }
                }
            }
        }
        __syncthreads();
    }

#pragma unroll
    for (int c = 0; c < 8; c++) {
        int co = co0 + (cg << 3) + c;
        float bv = bias[co];
#pragma unroll
        for (int p = 0; p < 4; p++) {
            float v = acc[p][c] + bv;
            if (relu) v = fmaxf(v, 0.f);
            out[((b*Cout + co)*Ho + oy0 + p)*Wo + ox0 + px] = v;
        }
    }
}

// ---------------------------------------------------------------------------
// ConvTranspose2d, k=4, s=2, p=1 via parity-tap decomposition (FFMA path).
// ---------------------------------------------------------------------------
template<int COG, int PXW, bool PACKED>
__global__ __launch_bounds__(COG*PXW)
void convT_tiled(const float* __restrict__ in, const float* __restrict__ w,
                 const float* __restrict__ bias, float* __restrict__ out,
                 int Cin, int Hin, int Win, int CoutW, int CoutReal, int act)
{
    constexpr int CIN_T = 8;
    constexpr int IH = 4;
    constexpr int IW = PXW/2 + 2;
    constexpr int NCO = COG*8;
    __shared__ __align__(16) float s_in[CIN_T*IH*IW];
    __shared__ __align__(16) float s_w [CIN_T*16*NCO];

    const int tid = threadIdx.x;
    const int px  = tid % PXW;
    const int cg  = tid / PXW;
    const int Ho = Hin*2, Wo = Win*2;
    const int hb  = Ho >> 2;
    const int b   = blockIdx.y / hb;
    const int oy0 = (blockIdx.y % hb) * 4;
    const int ox0 = blockIdx.x * PXW;
    const int co0 = blockIdx.z * NCO;
    const int m0  = oy0 >> 1;
    const int mx0 = ox0 >> 1;

    const int ox = ox0 + px;
    const int ex = ox & 1;
    const int mx = ox >> 1;
    int kxt[2], cxt[2];
    if (ex == 0) { kxt[0]=1; cxt[0]=mx-mx0+1; kxt[1]=3; cxt[1]=mx-mx0;   }
    else         { kxt[0]=0; cxt[0]=mx-mx0+2; kxt[1]=2; cxt[1]=mx-mx0+1; }

    float acc[4][8];
#pragma unroll
    for (int p = 0; p < 4; p++)
#pragma unroll
        for (int c = 0; c < 8; c++) acc[p][c] = 0.f;

    for (int ci0 = 0; ci0 < Cin; ci0 += CIN_T) {
        for (int idx = tid; idx < CIN_T*IH*IW; idx += COG*PXW) {
            int ci  = idx / (IH*IW);
            int rem = idx % (IH*IW);
            int r = rem / IW, c = rem % IW;
            int iy = m0 - 1 + r, ix = mx0 - 1 + c;
            float v = 0.f;
            if ((unsigned)iy < (unsigned)Hin && (unsigned)ix < (unsigned)Win)
                v = in[((b*Cin + ci0 + ci)*Hin + iy)*Win + ix];
            s_in[idx] = v;
        }
        for (int idx = tid; idx < CIN_T*16*NCO; idx += COG*PXW) {
            int co  = idx % NCO;
            int rem = idx / NCO;
            int kk  = rem % 16;
            int ci  = rem / 16;
            float v;
            if (PACKED) v = w[((ci0 + ci)*16 + kk)*8 + co];
            else        v = w[((ci0 + ci)*CoutW + co0 + co)*16 + kk];
            s_w[idx] = v;
        }
        __syncthreads();

        for (int ci = 0; ci < CIN_T; ci++) {
#pragma unroll
            for (int ey = 0; ey < 2; ey++) {
#pragma unroll
                for (int jy = 0; jy < 2; jy++) {
                    const int ky    = (ey==0) ? (jy==0 ? 1 : 3) : (jy==0 ? 0 : 2);
                    const int rbase = (ey==0) ? (jy==0 ? 1 : 0) : (jy==0 ? 2 : 1);
#pragma unroll
                    for (int jx = 0; jx < 2; jx++) {
                        int kk = ky*4 + kxt[jx];
                        const float4* wp =
                            (const float4*)(s_w + (ci*16 + kk)*NCO + cg*8);
                        float4 w0 = wp[0], w1 = wp[1];
#pragma unroll
                        for (int ph = 0; ph < 2; ph++) {
                            int p   = ey + ph*2;
                            int row = ph + rbase;
                            float iv = s_in[(ci*IH + row)*IW + cxt[jx]];
                            acc[p][0] += iv*w0.x; acc[p][1] += iv*w0.y;
                            acc[p][2] += iv*w0.z; acc[p][3] += iv*w0.w;
                            acc[p][4] += iv*w1.x; acc[p][5] += iv*w1.y;
                            acc[p][6] += iv*w1.z; acc[p][7] += iv*w1.w;
                        }
                    }
                }
            }
        }
        __syncthreads();
    }

#pragma unroll
    for (int c = 0; c < 8; c++) {
        int co = co0 + cg*8 + c;
        if (co >= CoutReal) continue;
        float bv = bias[co];
#pragma unroll
        for (int p = 0; p < 4; p++) {
            float v = acc[p][c] + bv;
            v = act ? tanhf(v) : fmaxf(v, 0.f);
            out[((b*CoutReal + co)*Ho + oy0 + p)*Wo + ox] = v;
        }
    }
}

// ---------------------------------------------------------------------------
// Helpers
// ---------------------------------------------------------------------------
__global__ void cnorm_kernel(const float* __restrict__ cb, float* __restrict__ cn) {
    int row  = (blockIdx.x*blockDim.x + threadIdx.x) >> 5;
    int lane = threadIdx.x & 31;
    if (row >= 4096) return;
    const float* p = cb + (size_t)row*256;
    float s = 0.f;
    for (int c = lane; c < 256; c += 32) { float v = p[c]; s += v*v; }
#pragma unroll
    for (int o = 16; o; o >>= 1) s += __shfl_down_sync(0xffffffffu, s, o);
    if (!lane) cn[row] = s;
}

__global__ void repack_w4(const float* __restrict__ w, float* __restrict__ wp) {
    int idx = blockIdx.x*256 + threadIdx.x;
    if (idx >= 64*16*8) return;
    int co = idx & 7, rem = idx >> 3;
    int kk = rem & 15, ci = rem >> 4;
    wp[idx] = (co < 3) ? w[(ci*3 + co)*16 + kk] : 0.f;
}

__global__ void zero_loss(double* l) { if (threadIdx.x < 4) l[threadIdx.x] = 0.0; }

__global__ void write_loss(const double* __restrict__ l, float* __restrict__ o) {
    if (threadIdx.x < 4)
        o[threadIdx.x] = (float)(l[threadIdx.x] * (1.0/(65536.0*256.0)));
}

// z (16,256,4096) NCHW -> tokens (65536,256); zero qsum
__global__ void z_to_tokens(const float* __restrict__ z,
                            float* __restrict__ resid, float* __restrict__ qsum)
{
    __shared__ float t[32][33];
    int b  = blockIdx.z;
    int s0 = blockIdx.x*32;
    int c0 = blockIdx.y*32;
    int x  = threadIdx.x;
    for (int y = threadIdx.y; y < 32; y += 8)
        t[y][x] = z[((size_t)b*256 + c0 + y)*4096 + s0 + x];
    __syncthreads();
    for (int y = threadIdx.y; y < 32; y += 8) {
        size_t o = ((size_t)b*4096 + s0 + y)*256 + c0 + x;
        resid[o] = t[x][y];
        qsum[o]  = 0.f;
    }
}

// tokens -> NCHW (two destinations: dec1 input + quantized output)
__global__ void tokens_to_z(const float* __restrict__ qsum,
                            float* __restrict__ z1, float* __restrict__ z2)
{
    __shared__ float t[32][33];
    int b  = blockIdx.z;
    int c0 = blockIdx.x*32;
    int s0 = blockIdx.y*32;
    int x  = threadIdx.x;
    for (int y = threadIdx.y; y < 32; y += 8)
        t[y][x] = qsum[((size_t)b*4096 + s0 + y)*256 + c0 + x];
    __syncthreads();
    for (int y = threadIdx.y; y < 32; y += 8) {
        float v = t[x][y];
        size_t o = ((size_t)b*256 + c0 + y)*4096 + s0 + x;
        z1[o] = v; z2[o] = v;
    }
}

// ---------------------------------------------------------------------------
// Launch
// ---------------------------------------------------------------------------
extern "C" void kernel_launch(void* const* d_in, const int* in_sizes, int n_in,
                              void* d_out, int out_size)
{
    const float* x   = (const float*)d_in[0];
    const float* ew1 = (const float*)d_in[1];  const float* eb1 = (const float*)d_in[2];
    const float* ew2 = (const float*)d_in[3];  const float* eb2 = (const float*)d_in[4];
    const float* ew3 = (const float*)d_in[5];  const float* eb3 = (const float*)d_in[6];
    const float* ew4 = (const float*)d_in[7];  const float* eb4 = (const float*)d_in[8];
    const float* cbs = (const float*)d_in[9];
    const float* dw1 = (const float*)d_in[10]; const float* db1 = (const float*)d_in[11];
    const float* dw2 = (const float*)d_in[12]; const float* db2 = (const float*)d_in[13];
    const float* dw3 = (const float*)d_in[14]; const float* db3 = (const float*)d_in[15];
    const float* dw4 = (const float*)d_in[16]; const float* db4 = (const float*)d_in[17];
    float* out = (float*)d_out;

    float *h1, *h2, *h3, *z, *resid, *qsum, *cnorm, *w4p, *d3;
    double* loss; unsigned* rowmin;
    cudaGetSymbolAddress((void**)&h1,    g_h1);
    cudaGetSymbolAddress((void**)&h2,    g_h2);
    cudaGetSymbolAddress((void**)&h3,    g_h3);
    cudaGetSymbolAddress((void**)&z,     g_z);
    cudaGetSymbolAddress((void**)&resid, g_resid);
    cudaGetSymbolAddress((void**)&qsum,  g_qsum);
    cudaGetSymbolAddress((void**)&loss,  g_loss);
    cudaGetSymbolAddress((void**)&cnorm, g_cnorm);
    cudaGetSymbolAddress((void**)&rowmin,g_rowmin);
    cudaGetSymbolAddress((void**)&w4p,   g_w4p);
    cudaGetSymbolAddress((void**)&d3,    g_d3);

    // output layout: recon | indices | commit_loss | quantized
    float* recO   = out;
    float* idxO   = out + 12582912;                 // 16*3*512*512
    float* lossO  = idxO + 262144;                  // 16*4*64*64
    float* quantO = lossO + 4;

    // dynamic smem for Phase A (2 planes of 128*33 words + 128 uint)
    const int PA_SMEM = 2*PLW*4 + 512;              // 34304
    cudaFuncSetAttribute(vq_gemm_approx, cudaFuncAttributeMaxDynamicSharedMemorySize, PA_SMEM);

    // prep
    repack_w4   <<<32, 256>>>(dw4, w4p);
    cnorm_kernel<<<512, 256>>>(cbs, cnorm);
    zero_loss   <<<1, 32>>>(loss);

    // ---- encoder (FFMA, exact) ----
    conv2d_tiled<4,2,4><<<dim3(8, 32*16, 1), 128>>>(x,  ew1, eb1, h1,   3, 256, 256,  64, 128, 128, 1, 1);
    conv2d_tiled<4,2,8><<<dim3(4, 16*16, 2), 128>>>(h1, ew2, eb2, h2,  64, 128, 128, 128,  64,  64, 1, 1);
    conv2d_tiled<3,1,8><<<dim3(4, 16*16, 4), 128>>>(h2, ew3, eb3, h3, 128,  64,  64, 256,  64,  64, 1, 1);
    conv2d_tiled<3,1,8><<<dim3(4, 16*16, 4), 128>>>(h3, ew4, eb4, z,  256,  64,  64, 256,  64,  64, 1, 0);

    // ---- residual VQ: single-MMA tf32 approx distances + exact FFMA rescore ----
    z_to_tokens<<<dim3(128, 8, 16), dim3(32, 8)>>>(z, resid, qsum);
    for (int s = 0; s < 4; s++) {
        init_rowmin     <<<64, 1024>>>(rowmin);
        vq_gemm_approx  <<<dim3(512, 8), 256, PA_SMEM>>>(resid, cbs + (size_t)s*1024*256,
                                                         cnorm + s*1024, d3, rowmin);
        vq_select_update<<<8192, 256>>>(d3, cbs + (size_t)s*1024*256, cnorm + s*1024,
                                        rowmin, resid, qsum, idxO, s, loss);
    }
    write_loss <<<1, 32>>>(loss, lossO);
    tokens_to_z<<<dim3(8, 128, 16), dim3(32, 8)>>>(qsum, z, quantO);

    // ---- decoder (FFMA, exact) ----
    conv2d_tiled<3,1,8><<<dim3(4, 16*16, 2), 128>>>(z, dw1, db1, h2, 256, 64, 64, 128, 64, 64, 1, 1);
    convT_tiled<8,  16, false><<<dim3( 8,  32*16, 1), 128>>>(h2, dw2, db2, h1, 128,  64,  64, 64, 64, 0);
    convT_tiled<8,  16, false><<<dim3(16,  64*16, 1), 128>>>(h1, dw3, db3, d3,  64, 128, 128, 64, 64, 0);
    convT_tiled<1, 128, true ><<<dim3( 4, 128*16, 1), 128>>>(d3, w4p, db4, recO, 64, 256, 256,  8,  3, 1);
}

// round 8
// speedup vs baseline: 1.7490x; 1.6127x over previous
#include <cuda_runtime.h>
#include <cstdint>

// ---------------------------------------------------------------------------
// Scratch (device globals — no allocation allowed)
// ---------------------------------------------------------------------------
__device__ float g_h1[16*64*128*128];          // enc1 out / dec2 out (reused)
__device__ float g_h2[16*128*64*64];           // enc2 out / dec1 out (reused)
__device__ float g_h3[16*256*64*64];           // enc3 out
__device__ float g_z [16*256*64*64];           // enc4 out (z) / quantized NCHW (reused)
__device__ float g_resid[65536*256];
__device__ float g_qsum [65536*256];
__device__ double g_loss[4];
__device__ float g_cnorm[4*1024];
__device__ unsigned g_rowmin[65536];
__device__ float g_w4p[64*16*8];               // dec_w4 repacked [ci][16][co(pad 8)]
__device__ float g_wt[1310720];                // conv weights repacked [tap][ci][co]
__device__ float g_wtT[196608];                // convT weights [parity][tap][ci][co]
__device__ float g_d3[16*64*256*256];          // dec3 out; ALSO the 65536x1024 D matrix

// ---------------------------------------------------------------------------
// tf32 helpers (approximate Phase-A path only; correctness never depends on it)
// ---------------------------------------------------------------------------
__device__ __forceinline__ uint32_t f2tf(float f) {
    uint32_t u;
    asm("cvt.rna.tf32.f32 %0, %1;" : "=r"(u) : "f"(f));
    return u;
}

__device__ __forceinline__ void mma_tf32(float* c, const uint32_t* a,
                                         uint32_t b0, uint32_t b1) {
    asm volatile(
        "mma.sync.aligned.m16n8k8.row.col.f32.tf32.tf32.f32 "
        "{%0,%1,%2,%3},{%4,%5,%6,%7},{%8,%9},{%0,%1,%2,%3};"
        : "+f"(c[0]), "+f"(c[1]), "+f"(c[2]), "+f"(c[3])
        : "r"(a[0]), "r"(a[1]), "r"(a[2]), "r"(a[3]), "r"(b0), "r"(b1));
}

// order-preserving float <-> uint32 (for atomicMin)
__device__ __forceinline__ unsigned fenc(float d) {
    unsigned u = __float_as_uint(d);
    return (u & 0x80000000u) ? ~u : (u | 0x80000000u);
}
__device__ __forceinline__ float fdec(unsigned e) {
    unsigned u = (e & 0x80000000u) ? (e & 0x7FFFFFFFu) : ~e;
    return __uint_as_float(u);
}

static const int PLW = 128*33;   // one smem plane in words (stride 33: conflict-free)

// ---------------------------------------------------------------------------
// Phase A: approximate distance matrix, single tf32 MMA (err ~5e-4 << 0.02).
// D[m,n] = cn[n] - 2 * R[m,:].cb[n,:]; also per-row min -> rowmin (atomicMin).
// ---------------------------------------------------------------------------
__global__ __launch_bounds__(256)
void vq_gemm_approx(const float* __restrict__ R, const float* __restrict__ cb,
                    const float* __restrict__ cn, float* __restrict__ D,
                    unsigned* __restrict__ rowmin)
{
    extern __shared__ uint32_t dyn[];
    uint32_t* sA = dyn;
    uint32_t* sB = dyn + PLW;
    unsigned* sMin = (unsigned*)(dyn + 2*PLW);

    const int tid  = threadIdx.x;
    const int lane = tid & 31;
    const int warp = tid >> 5;
    const int wm = warp & 1;
    const int wn = warp >> 1;
    const int m0 = blockIdx.x << 7;
    const int n0 = blockIdx.y << 7;

    float acc[4][4][4];
#pragma unroll
    for (int i = 0; i < 4; i++)
#pragma unroll
        for (int j = 0; j < 4; j++)
#pragma unroll
            for (int k = 0; k < 4; k++) acc[i][j][k] = 0.f;

    if (tid < 128) sMin[tid] = 0xFFFFFFFFu;

    for (int k0 = 0; k0 < 256; k0 += 32) {
#pragma unroll
        for (int i = 0; i < 4; i++) {
            int idx4 = tid + i*256;
            int m  = idx4 >> 3;
            int kq = idx4 & 7;
            int oa = m*33 + kq*4;
            float4 a = *(const float4*)(R  + (size_t)(m0 + m)*256 + k0 + kq*4);
            sA[oa+0] = f2tf(a.x); sA[oa+1] = f2tf(a.y);
            sA[oa+2] = f2tf(a.z); sA[oa+3] = f2tf(a.w);
            float4 b = *(const float4*)(cb + (size_t)(n0 + m)*256 + k0 + kq*4);
            sB[oa+0] = f2tf(b.x); sB[oa+1] = f2tf(b.y);
            sB[oa+2] = f2tf(b.z); sB[oa+3] = f2tf(b.w);
        }
        __syncthreads();

#pragma unroll
        for (int ks = 0; ks < 4; ks++) {
            const int kb = ks*8 + (lane & 3);
            uint32_t bf[4][2];
#pragma unroll
            for (int fn = 0; fn < 4; fn++) {
                int n = wn*32 + fn*8 + (lane >> 2);
                bf[fn][0] = sB[n*33 + kb];  bf[fn][1] = sB[n*33 + kb + 4];
            }
#pragma unroll
            for (int fm = 0; fm < 4; fm++) {
                int r = wm*64 + fm*16 + (lane >> 2);
                uint32_t af[4];
                af[0] = sA[r*33 + kb];     af[1] = sA[(r+8)*33 + kb];
                af[2] = sA[r*33 + kb+4];   af[3] = sA[(r+8)*33 + kb+4];
#pragma unroll
                for (int fn = 0; fn < 4; fn++)
                    mma_tf32(acc[fm][fn], af, bf[fn][0], bf[fn][1]);
            }
        }
        __syncthreads();
    }

    float cnv[4][2];
#pragma unroll
    for (int fn = 0; fn < 4; fn++) {
        int col = n0 + wn*32 + fn*8 + 2*(lane & 3);
        cnv[fn][0] = cn[col];
        cnv[fn][1] = cn[col + 1];
    }
#pragma unroll
    for (int fm = 0; fm < 4; fm++) {
#pragma unroll
        for (int h = 0; h < 2; h++) {
            int rl = wm*64 + fm*16 + (lane >> 2) + h*8;
            int rg = m0 + rl;
            float mn = 3.402823466e38f;
#pragma unroll
            for (int fn = 0; fn < 4; fn++) {
                int col = n0 + wn*32 + fn*8 + 2*(lane & 3);
                float2 v;
                v.x = cnv[fn][0] - 2.f*acc[fm][fn][h*2 + 0];
                v.y = cnv[fn][1] - 2.f*acc[fm][fn][h*2 + 1];
                mn = fminf(mn, fminf(v.x, v.y));
                *(float2*)(D + (size_t)rg*1024 + col) = v;
            }
            atomicMin(&sMin[rl], fenc(mn));
        }
    }
    __syncthreads();
    if (tid < 128) atomicMin(&rowmin[m0 + tid], sMin[tid]);
}

__global__ void init_rowmin(unsigned* rowmin) {
    rowmin[blockIdx.x*1024 + threadIdx.x] = 0xFFFFFFFFu;
}

// ---------------------------------------------------------------------------
// Phase B: one warp per token; exact-FFMA rescore of candidates within EPS of
// the approx row-min, lowest-index tie-break, fused vq_update.
// ---------------------------------------------------------------------------
__global__ __launch_bounds__(256)
void vq_select_update(const float* __restrict__ D, const float* __restrict__ cb,
                      const float* __restrict__ cn,
                      const unsigned* __restrict__ rowmin,
                      float* __restrict__ resid, float* __restrict__ qsum,
                      float* __restrict__ idx_out, int stage,
                      double* __restrict__ lossAcc)
{
    __shared__ double sLoss[8];
    const int warp = threadIdx.x >> 5;
    const int lane = threadIdx.x & 31;
    const int t = blockIdx.x*8 + warp;

    const float* drow = D + (size_t)t*1024;
    const float thr = fdec(rowmin[t]) + 0.02f;

    float4 r0 = *(const float4*)(resid + (size_t)t*256 + lane*8);
    float4 r1 = *(const float4*)(resid + (size_t)t*256 + lane*8 + 4);

    float bestd = 3.402823466e38f;
    int   bestn = 0;
    for (int j0 = 0; j0 < 1024; j0 += 32) {
        float dv = drow[j0 + lane];
        unsigned m = __ballot_sync(0xffffffffu, dv <= thr);
        while (m) {
            int src = __ffs(m) - 1; m &= m - 1;
            int j = j0 + src;
            const float* c = cb + (size_t)j*256;
            float4 c0 = *(const float4*)(c + lane*8);
            float4 c1 = *(const float4*)(c + lane*8 + 4);
            float dot = r0.x*c0.x + r0.y*c0.y + r0.z*c0.z + r0.w*c0.w
                      + r1.x*c1.x + r1.y*c1.y + r1.z*c1.z + r1.w*c1.w;
#pragma unroll
            for (int o = 16; o; o >>= 1)
                dot += __shfl_xor_sync(0xffffffffu, dot, o);
            float de = cn[j] - 2.f*dot;
            if (de < bestd) { bestd = de; bestn = j; }
        }
    }

    const float* q = cb + (size_t)bestn*256;
    float4 q0 = *(const float4*)(q + lane*8);
    float4 q1 = *(const float4*)(q + lane*8 + 4);
    float4 s0 = *(float4*)(qsum + (size_t)t*256 + lane*8);
    float4 s1 = *(float4*)(qsum + (size_t)t*256 + lane*8 + 4);

    float ls = 0.f;
    {
        float d;
        d = q0.x-r0.x; ls += d*d;  d = q0.y-r0.y; ls += d*d;
        d = q0.z-r0.z; ls += d*d;  d = q0.w-r0.w; ls += d*d;
        d = q1.x-r1.x; ls += d*d;  d = q1.y-r1.y; ls += d*d;
        d = q1.z-r1.z; ls += d*d;  d = q1.w-r1.w; ls += d*d;
    }
    s0.x += q0.x; s0.y += q0.y; s0.z += q0.z; s0.w += q0.w;
    s1.x += q1.x; s1.y += q1.y; s1.z += q1.z; s1.w += q1.w;
    r0.x -= q0.x; r0.y -= q0.y; r0.z -= q0.z; r0.w -= q0.w;
    r1.x -= q1.x; r1.y -= q1.y; r1.z -= q1.z; r1.w -= q1.w;
    *(float4*)(qsum  + (size_t)t*256 + lane*8)     = s0;
    *(float4*)(qsum  + (size_t)t*256 + lane*8 + 4) = s1;
    *(float4*)(resid + (size_t)t*256 + lane*8)     = r0;
    *(float4*)(resid + (size_t)t*256 + lane*8 + 4) = r1;

#pragma unroll
    for (int o = 16; o; o >>= 1) ls += __shfl_down_sync(0xffffffffu, ls, o);
    if (lane == 0) {
        sLoss[warp] = (double)ls;
        idx_out[(t >> 12)*16384 + stage*4096 + (t & 4095)] = (float)bestn;
    }
    __syncthreads();
    if (threadIdx.x == 0) {
        double tot = 0.0;
#pragma unroll
        for (int w = 0; w < 8; w++) tot += sLoss[w];
        atomicAdd(lossAcc + stage, tot);
    }
}

// ---------------------------------------------------------------------------
// Implicit-GEMM FFMA conv (3x3 s1 or 4x4 s2, pad 1). Output 64x64 per image.
// Tile: M=128 output pixels x N=128 couts, 256 threads, 8x8 per thread.
// Weights repacked wt[tap][ci][co].
// ---------------------------------------------------------------------------
template<int KSZ, int S>
__global__ __launch_bounds__(256)
void conv_ffma(const float* __restrict__ in, const float* __restrict__ wt,
               const float* __restrict__ bias, float* __restrict__ out,
               int Cin, int Hin, int Win, int Cout, int relu)
{
    __shared__ float sA[16*128];
    __shared__ float sB[16*128];
    const int tid = threadIdx.x;
    const int tx = tid & 15;          // pixel group (x8)
    const int ty = tid >> 4;          // cout group (x8)
    const int m0  = blockIdx.x << 7;  // 128 output pixels (2 rows of 64)
    const int co0 = blockIdx.y << 7;
    const int b   = m0 >> 12;         // HWout = 4096
    const int y0  = (m0 & 4095) >> 6;

    float acc[8][8];
#pragma unroll
    for (int i = 0; i < 8; i++)
#pragma unroll
        for (int j = 0; j < 8; j++) acc[i][j] = 0.f;

    for (int tap = 0; tap < KSZ*KSZ; tap++) {
        const int dy = tap/KSZ - 1, dx = tap%KSZ - 1;
        for (int ci0 = 0; ci0 < Cin; ci0 += 16) {
#pragma unroll
            for (int v = 0; v < 8; v++) {
                int idx = tid + v*256;
                int ci  = idx >> 7, pix = idx & 127;
                int iy = (y0 + (pix >> 6))*S + dy;
                int ix = (pix & 63)*S + dx;
                float val = 0.f;
                if ((unsigned)iy < (unsigned)Hin && (unsigned)ix < (unsigned)Win)
                    val = in[((size_t)(b*Cin + ci0 + ci)*Hin + iy)*Win + ix];
                sA[ci*128 + pix] = val;
            }
#pragma unroll
            for (int v = 0; v < 8; v++) {
                int idx = tid + v*256;
                int ci  = idx >> 7, n = idx & 127;
                sB[ci*128 + n] = wt[((size_t)tap*Cin + ci0 + ci)*Cout + co0 + n];
            }
            __syncthreads();

#pragma unroll
            for (int kk = 0; kk < 16; kk++) {
                float4 a0 = *(const float4*)&sA[kk*128 + tx*8];
                float4 a1 = *(const float4*)&sA[kk*128 + tx*8 + 4];
                float4 b0 = *(const float4*)&sB[kk*128 + ty*8];
                float4 b1 = *(const float4*)&sB[kk*128 + ty*8 + 4];
                float av[8] = {a0.x,a0.y,a0.z,a0.w,a1.x,a1.y,a1.z,a1.w};
                float bv[8] = {b0.x,b0.y,b0.z,b0.w,b1.x,b1.y,b1.z,b1.w};
#pragma unroll
                for (int i = 0; i < 8; i++)
#pragma unroll
                    for (int j = 0; j < 8; j++) acc[i][j] += av[i]*bv[j];
            }
            __syncthreads();
        }
    }

    const int yr = y0 + (tx >> 3);
    const int xc = (tx*8) & 63;
#pragma unroll
    for (int j = 0; j < 8; j++) {
        int co = co0 + ty*8 + j;
        float bv = bias[co];
        float4 v0, v1;
        v0.x = acc[0][j]+bv; v0.y = acc[1][j]+bv; v0.z = acc[2][j]+bv; v0.w = acc[3][j]+bv;
        v1.x = acc[4][j]+bv; v1.y = acc[5][j]+bv; v1.z = acc[6][j]+bv; v1.w = acc[7][j]+bv;
        if (relu) {
            v0.x = fmaxf(v0.x,0.f); v0.y = fmaxf(v0.y,0.f); v0.z = fmaxf(v0.z,0.f); v0.w = fmaxf(v0.w,0.f);
            v1.x = fmaxf(v1.x,0.f); v1.y = fmaxf(v1.y,0.f); v1.z = fmaxf(v1.z,0.f); v1.w = fmaxf(v1.w,0.f);
        }
        float* p = out + ((size_t)(b*Cout + co)*4096 + yr*64 + xc);
        *(float4*)p = v0;
        *(float4*)(p + 4) = v1;
    }
}

// ---------------------------------------------------------------------------
// Implicit-GEMM FFMA convT (k4 s2 p1), parity-decomposed: each output parity
// (blockIdx.z) is a 2x2 conv over the input grid. Cout = 64, relu.
// Tile: M=256 input pixels x N=64 couts, 256 threads, 8x8 per thread.
// Weights repacked wtT[parity][tap][ci][co].
// ---------------------------------------------------------------------------
__global__ __launch_bounds__(256)
void convT_ffma(const float* __restrict__ in, const float* __restrict__ wtT,
                const float* __restrict__ bias, float* __restrict__ out,
                int Cin, int Hin, int Win, int wsh, int hwsh)
{
    __shared__ float sA[16*256];
    __shared__ float sB[16*64];
    const int tid = threadIdx.x;
    const int tx = tid & 31;          // pixel group (x8) -> 256 px
    const int ty = tid >> 5;          // cout group (x8)  -> 64 co
    const int P0 = blockIdx.x << 8;
    const int b   = P0 >> hwsh;
    const int lp  = P0 & ((1 << hwsh) - 1);
    const int my0 = lp >> wsh;
    const int p  = blockIdx.z;
    const int ey = p >> 1, ex = p & 1;
    const float* wtp = wtT + (size_t)p*4*Cin*64;
    const int Wo  = Win*2;
    const int HWo = (Hin*Win)*4;

    float acc[8][8];
#pragma unroll
    for (int i = 0; i < 8; i++)
#pragma unroll
        for (int j = 0; j < 8; j++) acc[i][j] = 0.f;

    for (int t = 0; t < 4; t++) {
        const int jy = t >> 1, jx = t & 1;
        const int ry = (ey == 0) ? (jy == 0 ? 0 : -1) : (jy == 0 ? 1 : 0);
        const int rx = (ex == 0) ? (jx == 0 ? 0 : -1) : (jx == 0 ? 1 : 0);
        for (int ci0 = 0; ci0 < Cin; ci0 += 16) {
#pragma unroll
            for (int v = 0; v < 16; v++) {
                int idx = tid + v*256;
                int ci  = idx >> 8, pix = idx & 255;
                int iy = my0 + (pix >> wsh) + ry;
                int ix = (pix & (Win-1)) + rx;
                float val = 0.f;
                if ((unsigned)iy < (unsigned)Hin && (unsigned)ix < (unsigned)Win)
                    val = in[((size_t)(b*Cin + ci0 + ci)*Hin + iy)*Win + ix];
                sA[ci*256 + pix] = val;
            }
#pragma unroll
            for (int v = 0; v < 4; v++) {
                int idx = tid + v*256;
                int ci  = idx >> 6, n = idx & 63;
                sB[ci*64 + n] = wtp[((size_t)t*Cin + ci0 + ci)*64 + n];
            }
            __syncthreads();

#pragma unroll
            for (int kk = 0; kk < 16; kk++) {
                float4 a0 = *(const float4*)&sA[kk*256 + tx*8];
                float4 a1 = *(const float4*)&sA[kk*256 + tx*8 + 4];
                float4 b0 = *(const float4*)&sB[kk*64 + ty*8];
                float4 b1 = *(const float4*)&sB[kk*64 + ty*8 + 4];
                float av[8] = {a0.x,a0.y,a0.z,a0.w,a1.x,a1.y,a1.z,a1.w};
                float bv[8] = {b0.x,b0.y,b0.z,b0.w,b1.x,b1.y,b1.z,b1.w};
#pragma unroll
                for (int i = 0; i < 8; i++)
#pragma unroll
                    for (int j = 0; j < 8; j++) acc[i][j] += av[i]*bv[j];
            }
            __syncthreads();
        }
    }

    const int m  = my0 + ((tx*8) >> wsh);
    const int oy = 2*m + ey;
#pragma unroll
    for (int j = 0; j < 8; j++) {
        int co = ty*8 + j;
        float bv = bias[co];
        float* p0 = out + ((size_t)(b*64 + co)*HWo + oy*Wo + ex);
#pragma unroll
        for (int i = 0; i < 8; i++) {
            int mx = (tx*8 + i) & (Win-1);
            p0[2*mx] = fmaxf(acc[i][j] + bv, 0.f);
        }
    }
}

// ---------------------------------------------------------------------------
// Weight repacks
// ---------------------------------------------------------------------------
__global__ void repack_conv_w(const float* __restrict__ w, float* __restrict__ wt,
                              int Cin, int Cout, int KK)
{
    int idx = blockIdx.x*256 + threadIdx.x;
    int total = Cin*Cout*KK;
    if (idx >= total) return;
    int co = idx % Cout; int r = idx / Cout;
    int ci = r % Cin;    int tap = r / Cin;
    wt[idx] = w[(co*Cin + ci)*KK + tap];
}

__global__ void repack_convT_w(const float* __restrict__ w, float* __restrict__ wtT,
                               int Cin, int Cout)
{
    int idx = blockIdx.x*256 + threadIdx.x;
    int total = 16*Cin*Cout;
    if (idx >= total) return;
    int co = idx % Cout; int r = idx / Cout;
    int ci = r % Cin;    int pt = r / Cin;
    int p = pt >> 2, t = pt & 3;
    int ey = p >> 1, ex = p & 1;
    int jy = t >> 1, jx = t & 1;
    int ky = (ey == 0) ? (jy == 0 ? 1 : 3) : (jy == 0 ? 0 : 2);
    int kx = (ex == 0) ? (jx == 0 ? 1 : 3) : (jx == 0 ? 0 : 2);
    wtT[idx] = w[((ci*Cout + co)*4 + ky)*4 + kx];
}

// ---------------------------------------------------------------------------
// Direct conv (FFMA) — enc1 only (Cin=3).
// ---------------------------------------------------------------------------
template<int K, int S, int CIN_T>
__global__ __launch_bounds__(128)
void conv2d_tiled(const float* __restrict__ in, const float* __restrict__ w,
                  const float* __restrict__ bias, float* __restrict__ out,
                  int Cin, int H, int W, int Cout, int Ho, int Wo,
                  int pad, int relu)
{
    constexpr int IH = 3*S + K;
    constexpr int IW = 15*S + K;
    constexpr int KK = K*K;
    __shared__ __align__(16) float s_in[CIN_T*IH*IW];
    __shared__ __align__(16) float s_w [CIN_T*KK*64];

    const int tid = threadIdx.x;
    const int px  = tid & 15;
    const int cg  = tid >> 4;
    const int hb  = Ho >> 2;
    const int b   = blockIdx.y / hb;
    const int oy0 = (blockIdx.y % hb) * 4;
    const int ox0 = blockIdx.x * 16;
    const int co0 = blockIdx.z * 64;
    const int iy0 = oy0*S - pad;
    const int ix0 = ox0*S - pad;

    float acc[4][8];
#pragma unroll
    for (int p = 0; p < 4; p++)
#pragma unroll
        for (int c = 0; c < 8; c++) acc[p][c] = 0.f;

    for (int ci0 = 0; ci0 < Cin; ci0 += CIN_T) {
        for (int idx = tid; idx < CIN_T*IH*IW; idx += 128) {
            int ci  = idx / (IH*IW);
            int rem = idx % (IH*IW);
            int r   = rem / IW, c = rem % IW;
            int iy  = iy0 + r, ix = ix0 + c;
            float v = 0.f;
            if ((unsigned)iy < (unsigned)H && (unsigned)ix < (unsigned)W &&
                (ci0 + ci) < Cin)
                v = in[((b*Cin + ci0 + ci)*H + iy)*W + ix];
            s_in[idx] = v;
        }
        for (int idx = tid; idx < CIN_T*KK*64; idx += 128) {
            int co  = idx & 63;
            int rem = idx >> 6;
            int kk  = rem % KK;
            int ci  = rem / KK;
            float v = 0.f;
            if ((ci0 + ci) < Cin)
                v = w[((co0 + co)*Cin + ci0 + ci)*KK + kk];
            s_w[idx] = v;
        }
        __syncthreads();

        for (int ci = 0; ci < CIN_T; ci++) {
#pragma unroll
            for (int kh = 0; kh < K; kh++) {
#pragma unroll
                for (int kw = 0; kw < K; kw++) {
                    const float4* wp =
                        (const float4*)(s_w + ((ci*KK + kh*K + kw) << 6) + (cg << 3));
                    float4 w0 = wp[0], w1 = wp[1];
#pragma unroll
                    for (int p = 0; p < 4; p++) {
                        float iv = s_in[(ci*IH + p*S + kh)*IW + px*S + kw];
                        acc[p][0] += iv*w0.x; acc[p][1] += iv*w0.y;
                        acc[p][2] += iv*w0.z; acc[p][3] += iv*w0.w;
                        acc[p][4] += iv*w1.x; acc[p][5] += iv*w1.y;
                        acc[p][6] += iv*w1.z; acc[p][7] += iv*w1.w;
                    }
                }
            }
        }
        __syncthreads();
    }

#pragma unroll
    for (int c = 0; c < 8; c++) {
        int co = co0 + (cg << 3) + c;
        float bv = bias[co];
#pragma unroll
        for (int p = 0; p < 4; p++) {
            float v = acc[p][c] + bv;
            if (relu) v = fmaxf(v, 0.f);
            out[((b*Cout + co)*Ho + oy0 + p)*Wo + ox0 + px] = v;
        }
    }
}

// ---------------------------------------------------------------------------
// ConvTranspose2d direct (FFMA) — convT4 only (Cout=3, tanh).
// ---------------------------------------------------------------------------
template<int COG, int PXW, bool PACKED>
__global__ __launch_bounds__(COG*PXW)
void convT_tiled(const float* __restrict__ in, const float* __restrict__ w,
                 const float* __restrict__ bias, float* __restrict__ out,
                 int Cin, int Hin, int Win, int CoutW, int CoutReal, int act)
{
    constexpr int CIN_T = 8;
    constexpr int IH = 4;
    constexpr int IW = PXW/2 + 2;
    constexpr int NCO = COG*8;
    __shared__ __align__(16) float s_in[CIN_T*IH*IW];
    __shared__ __align__(16) float s_w [CIN_T*16*NCO];

    const int tid = threadIdx.x;
    const int px  = tid % PXW;
    const int cg  = tid / PXW;
    const int Ho = Hin*2, Wo = Win*2;
    const int hb  = Ho >> 2;
    const int b   = blockIdx.y / hb;
    const int oy0 = (blockIdx.y % hb) * 4;
    const int ox0 = blockIdx.x * PXW;
    const int co0 = blockIdx.z * NCO;
    const int m0  = oy0 >> 1;
    const int mx0 = ox0 >> 1;

    const int ox = ox0 + px;
    const int ex = ox & 1;
    const int mx = ox >> 1;
    int kxt[2], cxt[2];
    if (ex == 0) { kxt[0]=1; cxt[0]=mx-mx0+1; kxt[1]=3; cxt[1]=mx-mx0;   }
    else         { kxt[0]=0; cxt[0]=mx-mx0+2; kxt[1]=2; cxt[1]=mx-mx0+1; }

    float acc[4][8];
#pragma unroll
    for (int p = 0; p < 4; p++)
#pragma unroll
        for (int c = 0; c < 8; c++) acc[p][c] = 0.f;

    for (int ci0 = 0; ci0 < Cin; ci0 += CIN_T) {
        for (int idx = tid; idx < CIN_T*IH*IW; idx += COG*PXW) {
            int ci  = idx / (IH*IW);
            int rem = idx % (IH*IW);
            int r = rem / IW, c = rem % IW;
            int iy = m0 - 1 + r, ix = mx0 - 1 + c;
            float v = 0.f;
            if ((unsigned)iy < (unsigned)Hin && (unsigned)ix < (unsigned)Win)
                v = in[((b*Cin + ci0 + ci)*Hin + iy)*Win + ix];
            s_in[idx] = v;
        }
        for (int idx = tid; idx < CIN_T*16*NCO; idx += COG*PXW) {
            int co  = idx % NCO;
            int rem = idx / NCO;
            int kk  = rem % 16;
            int ci  = rem / 16;
            float v;
            if (PACKED) v = w[((ci0 + ci)*16 + kk)*8 + co];
            else        v = w[((ci0 + ci)*CoutW + co0 + co)*16 + kk];
            s_w[idx] = v;
        }
        __syncthreads();

        for (int ci = 0; ci < CIN_T; ci++) {
#pragma unroll
            for (int ey = 0; ey < 2; ey++) {
#pragma unroll
                for (int jy = 0; jy < 2; jy++) {
                    const int ky    = (ey==0) ? (jy==0 ? 1 : 3) : (jy==0 ? 0 : 2);
                    const int rbase = (ey==0) ? (jy==0 ? 1 : 0) : (jy==0 ? 2 : 1);
#pragma unroll
                    for (int jx = 0; jx < 2; jx++) {
                        int kk = ky*4 + kxt[jx];
                        const float4* wp =
                            (const float4*)(s_w + (ci*16 + kk)*NCO + cg*8);
                        float4 w0 = wp[0], w1 = wp[1];
#pragma unroll
                        for (int ph = 0; ph < 2; ph++) {
                            int p   = ey + ph*2;
                            int row = ph + rbase;
                            float iv = s_in[(ci*IH + row)*IW + cxt[jx]];
                            acc[p][0] += iv*w0.x; acc[p][1] += iv*w0.y;
                            acc[p][2] += iv*w0.z; acc[p][3] += iv*w0.w;
                            acc[p][4] += iv*w1.x; acc[p][5] += iv*w1.y;
                            acc[p][6] += iv*w1.z; acc[p][7] += iv*w1.w;
                        }
                    }
                }
            }
        }
        __syncthreads();
    }

#pragma unroll
    for (int c = 0; c < 8; c++) {
        int co = co0 + cg*8 + c;
        if (co >= CoutReal) continue;
        float bv = bias[co];
#pragma unroll
        for (int p = 0; p < 4; p++) {
            float v = acc[p][c] + bv;
            v = act ? tanhf(v) : fmaxf(v, 0.f);
            out[((b*CoutReal + co)*Ho + oy0 + p)*Wo + ox] = v;
        }
    }
}

// ---------------------------------------------------------------------------
// Helpers
// ---------------------------------------------------------------------------
__global__ void cnorm_kernel(const float* __restrict__ cb, float* __restrict__ cn) {
    int row  = (blockIdx.x*blockDim.x + threadIdx.x) >> 5;
    int lane = threadIdx.x & 31;
    if (row >= 4096) return;
    const float* p = cb + (size_t)row*256;
    float s = 0.f;
    for (int c = lane; c < 256; c += 32) { float v = p[c]; s += v*v; }
#pragma unroll
    for (int o = 16; o; o >>= 1) s += __shfl_down_sync(0xffffffffu, s, o);
    if (!lane) cn[row] = s;
}

__global__ void repack_w4(const float* __restrict__ w, float* __restrict__ wp) {
    int idx = blockIdx.x*256 + threadIdx.x;
    if (idx >= 64*16*8) return;
    int co = idx & 7, rem = idx >> 3;
    int kk = rem & 15, ci = rem >> 4;
    wp[idx] = (co < 3) ? w[(ci*3 + co)*16 + kk] : 0.f;
}

__global__ void zero_loss(double* l) { if (threadIdx.x < 4) l[threadIdx.x] = 0.0; }

__global__ void write_loss(const double* __restrict__ l, float* __restrict__ o) {
    if (threadIdx.x < 4)
        o[threadIdx.x] = (float)(l[threadIdx.x] * (1.0/(65536.0*256.0)));
}

__global__ void z_to_tokens(const float* __restrict__ z,
                            float* __restrict__ resid, float* __restrict__ qsum)
{
    __shared__ float t[32][33];
    int b  = blockIdx.z;
    int s0 = blockIdx.x*32;
    int c0 = blockIdx.y*32;
    int x  = threadIdx.x;
    for (int y = threadIdx.y; y < 32; y += 8)
        t[y][x] = z[((size_t)b*256 + c0 + y)*4096 + s0 + x];
    __syncthreads();
    for (int y = threadIdx.y; y < 32; y += 8) {
        size_t o = ((size_t)b*4096 + s0 + y)*256 + c0 + x;
        resid[o] = t[x][y];
        qsum[o]  = 0.f;
    }
}

__global__ void tokens_to_z(const float* __restrict__ qsum,
                            float* __restrict__ z1, float* __restrict__ z2)
{
    __shared__ float t[32][33];
    int b  = blockIdx.z;
    int c0 = blockIdx.x*32;
    int s0 = blockIdx.y*32;
    int x  = threadIdx.x;
    for (int y = threadIdx.y; y < 32; y += 8)
        t[y][x] = qsum[((size_t)b*4096 + s0 + y)*256 + c0 + x];
    __syncthreads();
    for (int y = threadIdx.y; y < 32; y += 8) {
        float v = t[x][y];
        size_t o = ((size_t)b*256 + c0 + y)*4096 + s0 + x;
        z1[o] = v; z2[o] = v;
    }
}

// ---------------------------------------------------------------------------
// Launch
// ---------------------------------------------------------------------------
extern "C" void kernel_launch(void* const* d_in, const int* in_sizes, int n_in,
                              void* d_out, int out_size)
{
    const float* x   = (const float*)d_in[0];
    const float* ew1 = (const float*)d_in[1];  const float* eb1 = (const float*)d_in[2];
    const float* ew2 = (const float*)d_in[3];  const float* eb2 = (const float*)d_in[4];
    const float* ew3 = (const float*)d_in[5];  const float* eb3 = (const float*)d_in[6];
    const float* ew4 = (const float*)d_in[7];  const float* eb4 = (const float*)d_in[8];
    const float* cbs = (const float*)d_in[9];
    const float* dw1 = (const float*)d_in[10]; const float* db1 = (const float*)d_in[11];
    const float* dw2 = (const float*)d_in[12]; const float* db2 = (const float*)d_in[13];
    const float* dw3 = (const float*)d_in[14]; const float* db3 = (const float*)d_in[15];
    const float* dw4 = (const float*)d_in[16]; const float* db4 = (const float*)d_in[17];
    float* out = (float*)d_out;

    float *h1, *h2, *h3, *z, *resid, *qsum, *cnorm, *w4p, *wt, *wtT, *d3;
    double* loss; unsigned* rowmin;
    cudaGetSymbolAddress((void**)&h1,    g_h1);
    cudaGetSymbolAddress((void**)&h2,    g_h2);
    cudaGetSymbolAddress((void**)&h3,    g_h3);
    cudaGetSymbolAddress((void**)&z,     g_z);
    cudaGetSymbolAddress((void**)&resid, g_resid);
    cudaGetSymbolAddress((void**)&qsum,  g_qsum);
    cudaGetSymbolAddress((void**)&loss,  g_loss);
    cudaGetSymbolAddress((void**)&cnorm, g_cnorm);
    cudaGetSymbolAddress((void**)&rowmin,g_rowmin);
    cudaGetSymbolAddress((void**)&w4p,   g_w4p);
    cudaGetSymbolAddress((void**)&wt,    g_wt);
    cudaGetSymbolAddress((void**)&wtT,   g_wtT);
    cudaGetSymbolAddress((void**)&d3,    g_d3);

    float* wt_e2  = wt;                               // 16*64*128  = 131072
    float* wt_e3  = wt + 131072;                      // 9*128*256  = 294912
    float* wt_e4  = wt + 131072 + 294912;             // 9*256*256  = 589824
    float* wt_d1  = wt + 131072 + 294912 + 589824;    // 9*256*128  = 294912
    float* wtT_d2 = wtT;                              // 16*128*64  = 131072
    float* wtT_d3 = wtT + 131072;                     // 16*64*64   = 65536

    // output layout: recon | indices | commit_loss | quantized
    float* recO   = out;
    float* idxO   = out + 12582912;
    float* lossO  = idxO + 262144;
    float* quantO = lossO + 4;

    const int PA_SMEM = 2*PLW*4 + 512;
    cudaFuncSetAttribute(vq_gemm_approx, cudaFuncAttributeMaxDynamicSharedMemorySize, PA_SMEM);

    // prep
    repack_w4     <<<32, 256>>>(dw4, w4p);
    cnorm_kernel  <<<512, 256>>>(cbs, cnorm);
    zero_loss     <<<1, 32>>>(loss);
    repack_conv_w <<<(131072+255)/256, 256>>>(ew2, wt_e2,  64, 128, 16);
    repack_conv_w <<<(294912+255)/256, 256>>>(ew3, wt_e3, 128, 256,  9);
    repack_conv_w <<<(589824+255)/256, 256>>>(ew4, wt_e4, 256, 256,  9);
    repack_conv_w <<<(294912+255)/256, 256>>>(dw1, wt_d1, 256, 128,  9);
    repack_convT_w<<<(131072+255)/256, 256>>>(dw2, wtT_d2, 128, 64);
    repack_convT_w<<<( 65536+255)/256, 256>>>(dw3, wtT_d3,  64, 64);

    // ---- encoder ----
    conv2d_tiled<4,2,4><<<dim3(8, 32*16, 1), 128>>>(x, ew1, eb1, h1, 3, 256, 256, 64, 128, 128, 1, 1);
    conv_ffma<4,2><<<dim3(512, 1), 256>>>(h1, wt_e2, eb2, h2,  64, 128, 128, 128, 1);
    conv_ffma<3,1><<<dim3(512, 2), 256>>>(h2, wt_e3, eb3, h3, 128,  64,  64, 256, 1);
    conv_ffma<3,1><<<dim3(512, 2), 256>>>(h3, wt_e4, eb4, z,  256,  64,  64, 256, 0);

    // ---- residual VQ: single-MMA tf32 approx distances + exact FFMA rescore ----
    z_to_tokens<<<dim3(128, 8, 16), dim3(32, 8)>>>(z, resid, qsum);
    for (int s = 0; s < 4; s++) {
        init_rowmin     <<<64, 1024>>>(rowmin);
        vq_gemm_approx  <<<dim3(512, 8), 256, PA_SMEM>>>(resid, cbs + (size_t)s*1024*256,
                                                         cnorm + s*1024, d3, rowmin);
        vq_select_update<<<8192, 256>>>(d3, cbs + (size_t)s*1024*256, cnorm + s*1024,
                                        rowmin, resid, qsum, idxO, s, loss);
    }
    write_loss <<<1, 32>>>(loss, lossO);
    tokens_to_z<<<dim3(8, 128, 16), dim3(32, 8)>>>(qsum, z, quantO);

    // ---- decoder ----
    conv_ffma<3,1><<<dim3(512, 1), 256>>>(z, wt_d1, db1, h2, 256, 64, 64, 128, 1);
    convT_ffma<<<dim3( 256, 1, 4), 256>>>(h2, wtT_d2, db2, h1, 128,  64,  64, 6, 12);
    convT_ffma<<<dim3(1024, 1, 4), 256>>>(h1, wtT_d3, db3, d3,  64, 128, 128, 7, 14);
    convT_tiled<1, 128, true><<<dim3(4, 128*16, 1), 128>>>(d3, w4p, db4, recO, 64, 256, 256, 8, 3, 1);
}

// round 9
// speedup vs baseline: 1.7795x; 1.0174x over previous
#include <cuda_runtime.h>
#include <cuda_bf16.h>
#include <cstdint>

// ---------------------------------------------------------------------------
// Scratch (device globals — no allocation allowed)
// ---------------------------------------------------------------------------
__device__ float g_h1[16*64*128*128];          // enc1 out / dec2 out (reused)
__device__ float g_h2[16*128*64*64];           // enc2 out / dec1 out (reused)
__device__ float g_h3[16*256*64*64];           // enc3 out
__device__ float g_z [16*256*64*64];           // enc4 out (z) / quantized NCHW (reused)
__device__ float g_resid[65536*256];
__device__ float g_qsum [65536*256];
__device__ double g_loss[4];
__device__ float g_cnorm[4*1024];
__device__ unsigned g_rowmin[65536];
__device__ float g_w4p[9*64*16];               // dec_w4 repacked [tau][ci][12 pad 16]
__device__ float g_wt[1310720];                // conv weights repacked [tap][ci][co]
__device__ float g_wtT[196608];                // convT weights [parity][tap][ci][co]
__device__ float g_d3[16*64*256*256];          // dec3 out; ALSO the 65536x1024 D (bf16)

// ---------------------------------------------------------------------------
// tf32 helpers (approximate Phase-A path only; correctness never depends on it)
// ---------------------------------------------------------------------------
__device__ __forceinline__ uint32_t f2tf(float f) {
    uint32_t u;
    asm("cvt.rna.tf32.f32 %0, %1;" : "=r"(u) : "f"(f));
    return u;
}

__device__ __forceinline__ void mma_tf32(float* c, const uint32_t* a,
                                         uint32_t b0, uint32_t b1) {
    asm volatile(
        "mma.sync.aligned.m16n8k8.row.col.f32.tf32.tf32.f32 "
        "{%0,%1,%2,%3},{%4,%5,%6,%7},{%8,%9},{%0,%1,%2,%3};"
        : "+f"(c[0]), "+f"(c[1]), "+f"(c[2]), "+f"(c[3])
        : "r"(a[0]), "r"(a[1]), "r"(a[2]), "r"(a[3]), "r"(b0), "r"(b1));
}

// order-preserving float <-> uint32 (for atomicMin)
__device__ __forceinline__ unsigned fenc(float d) {
    unsigned u = __float_as_uint(d);
    return (u & 0x80000000u) ? ~u : (u | 0x80000000u);
}
__device__ __forceinline__ float fdec(unsigned e) {
    unsigned u = (e & 0x80000000u) ? (e & 0x7FFFFFFFu) : ~e;
    return __uint_as_float(u);
}

static const int PLW = 128*33;   // one smem plane in words (stride 33: conflict-free)

// ---------------------------------------------------------------------------
// Phase A: approximate distance matrix, single tf32 MMA, D stored as bf16.
// D[m,n] = cn[n] - 2 * R[m,:].cb[n,:]; per-row min -> rowmin (atomicMin).
// ---------------------------------------------------------------------------
__global__ __launch_bounds__(256)
void vq_gemm_approx(const float* __restrict__ R, const float* __restrict__ cb,
                    const float* __restrict__ cn, __nv_bfloat16* __restrict__ D,
                    unsigned* __restrict__ rowmin)
{
    extern __shared__ uint32_t dyn[];
    uint32_t* sA = dyn;
    uint32_t* sB = dyn + PLW;
    unsigned* sMin = (unsigned*)(dyn + 2*PLW);

    const int tid  = threadIdx.x;
    const int lane = tid & 31;
    const int warp = tid >> 5;
    const int wm = warp & 1;
    const int wn = warp >> 1;
    const int m0 = blockIdx.x << 7;
    const int n0 = blockIdx.y << 7;

    float acc[4][4][4];
#pragma unroll
    for (int i = 0; i < 4; i++)
#pragma unroll
        for (int j = 0; j < 4; j++)
#pragma unroll
            for (int k = 0; k < 4; k++) acc[i][j][k] = 0.f;

    if (tid < 128) sMin[tid] = 0xFFFFFFFFu;

    for (int k0 = 0; k0 < 256; k0 += 32) {
#pragma unroll
        for (int i = 0; i < 4; i++) {
            int idx4 = tid + i*256;
            int m  = idx4 >> 3;
            int kq = idx4 & 7;
            int oa = m*33 + kq*4;
            float4 a = *(const float4*)(R  + (size_t)(m0 + m)*256 + k0 + kq*4);
            sA[oa+0] = f2tf(a.x); sA[oa+1] = f2tf(a.y);
            sA[oa+2] = f2tf(a.z); sA[oa+3] = f2tf(a.w);
            float4 b = *(const float4*)(cb + (size_t)(n0 + m)*256 + k0 + kq*4);
            sB[oa+0] = f2tf(b.x); sB[oa+1] = f2tf(b.y);
            sB[oa+2] = f2tf(b.z); sB[oa+3] = f2tf(b.w);
        }
        __syncthreads();

#pragma unroll
        for (int ks = 0; ks < 4; ks++) {
            const int kb = ks*8 + (lane & 3);
            uint32_t bf[4][2];
#pragma unroll
            for (int fn = 0; fn < 4; fn++) {
                int n = wn*32 + fn*8 + (lane >> 2);
                bf[fn][0] = sB[n*33 + kb];  bf[fn][1] = sB[n*33 + kb + 4];
            }
#pragma unroll
            for (int fm = 0; fm < 4; fm++) {
                int r = wm*64 + fm*16 + (lane >> 2);
                uint32_t af[4];
                af[0] = sA[r*33 + kb];     af[1] = sA[(r+8)*33 + kb];
                af[2] = sA[r*33 + kb+4];   af[3] = sA[(r+8)*33 + kb+4];
#pragma unroll
                for (int fn = 0; fn < 4; fn++)
                    mma_tf32(acc[fm][fn], af, bf[fn][0], bf[fn][1]);
            }
        }
        __syncthreads();
    }

    float cnv[4][2];
#pragma unroll
    for (int fn = 0; fn < 4; fn++) {
        int col = n0 + wn*32 + fn*8 + 2*(lane & 3);
        cnv[fn][0] = cn[col];
        cnv[fn][1] = cn[col + 1];
    }
#pragma unroll
    for (int fm = 0; fm < 4; fm++) {
#pragma unroll
        for (int h = 0; h < 2; h++) {
            int rl = wm*64 + fm*16 + (lane >> 2) + h*8;
            int rg = m0 + rl;
            float mn = 3.402823466e38f;
#pragma unroll
            for (int fn = 0; fn < 4; fn++) {
                int col = n0 + wn*32 + fn*8 + 2*(lane & 3);
                float vx = cnv[fn][0] - 2.f*acc[fm][fn][h*2 + 0];
                float vy = cnv[fn][1] - 2.f*acc[fm][fn][h*2 + 1];
                mn = fminf(mn, fminf(vx, vy));
                *(__nv_bfloat162*)(D + (size_t)rg*1024 + col) =
                    __floats2bfloat162_rn(vx, vy);
            }
            atomicMin(&sMin[rl], fenc(mn));
        }
    }
    __syncthreads();
    if (tid < 128) atomicMin(&rowmin[m0 + tid], sMin[tid]);
}

__global__ void init_rowmin(unsigned* rowmin) {
    rowmin[blockIdx.x*1024 + threadIdx.x] = 0xFFFFFFFFu;
}

// ---------------------------------------------------------------------------
// Phase B: one warp per token; exact-FFMA rescore of candidates within EPS of
// the approx row-min, lowest-index tie-break, fused vq_update.
// ---------------------------------------------------------------------------
__global__ __launch_bounds__(256)
void vq_select_update(const __nv_bfloat16* __restrict__ D, const float* __restrict__ cb,
                      const float* __restrict__ cn,
                      const unsigned* __restrict__ rowmin,
                      float* __restrict__ resid, float* __restrict__ qsum,
                      float* __restrict__ idx_out, int stage,
                      double* __restrict__ lossAcc)
{
    __shared__ double sLoss[8];
    const int warp = threadIdx.x >> 5;
    const int lane = threadIdx.x & 31;
    const int t = blockIdx.x*8 + warp;

    const __nv_bfloat16* drow = D + (size_t)t*1024;
    const float thr = fdec(rowmin[t]) + 0.03f;   // covers mma err + bf16 rounding

    float4 r0 = *(const float4*)(resid + (size_t)t*256 + lane*8);
    float4 r1 = *(const float4*)(resid + (size_t)t*256 + lane*8 + 4);

    float bestd = 3.402823466e38f;
    int   bestn = 0;
    for (int j0 = 0; j0 < 1024; j0 += 32) {
        float dv = __bfloat162float(drow[j0 + lane]);
        unsigned m = __ballot_sync(0xffffffffu, dv <= thr);
        while (m) {
            int src = __ffs(m) - 1; m &= m - 1;
            int j = j0 + src;
            const float* c = cb + (size_t)j*256;
            float4 c0 = *(const float4*)(c + lane*8);
            float4 c1 = *(const float4*)(c + lane*8 + 4);
            float dot = r0.x*c0.x + r0.y*c0.y + r0.z*c0.z + r0.w*c0.w
                      + r1.x*c1.x + r1.y*c1.y + r1.z*c1.z + r1.w*c1.w;
#pragma unroll
            for (int o = 16; o; o >>= 1)
                dot += __shfl_xor_sync(0xffffffffu, dot, o);
            float de = cn[j] - 2.f*dot;
            if (de < bestd) { bestd = de; bestn = j; }
        }
    }

    const float* q = cb + (size_t)bestn*256;
    float4 q0 = *(const float4*)(q + lane*8);
    float4 q1 = *(const float4*)(q + lane*8 + 4);
    float4 s0 = *(float4*)(qsum + (size_t)t*256 + lane*8);
    float4 s1 = *(float4*)(qsum + (size_t)t*256 + lane*8 + 4);

    float ls = 0.f;
    {
        float d;
        d = q0.x-r0.x; ls += d*d;  d = q0.y-r0.y; ls += d*d;
        d = q0.z-r0.z; ls += d*d;  d = q0.w-r0.w; ls += d*d;
        d = q1.x-r1.x; ls += d*d;  d = q1.y-r1.y; ls += d*d;
        d = q1.z-r1.z; ls += d*d;  d = q1.w-r1.w; ls += d*d;
    }
    s0.x += q0.x; s0.y += q0.y; s0.z += q0.z; s0.w += q0.w;
    s1.x += q1.x; s1.y += q1.y; s1.z += q1.z; s1.w += q1.w;
    r0.x -= q0.x; r0.y -= q0.y; r0.z -= q0.z; r0.w -= q0.w;
    r1.x -= q1.x; r1.y -= q1.y; r1.z -= q1.z; r1.w -= q1.w;
    *(float4*)(qsum  + (size_t)t*256 + lane*8)     = s0;
    *(float4*)(qsum  + (size_t)t*256 + lane*8 + 4) = s1;
    *(float4*)(resid + (size_t)t*256 + lane*8)     = r0;
    *(float4*)(resid + (size_t)t*256 + lane*8 + 4) = r1;

#pragma unroll
    for (int o = 16; o; o >>= 1) ls += __shfl_down_sync(0xffffffffu, ls, o);
    if (lane == 0) {
        sLoss[warp] = (double)ls;
        idx_out[(t >> 12)*16384 + stage*4096 + (t & 4095)] = (float)bestn;
    }
    __syncthreads();
    if (threadIdx.x == 0) {
        double tot = 0.0;
#pragma unroll
        for (int w = 0; w < 8; w++) tot += sLoss[w];
        atomicAdd(lossAcc + stage, tot);
    }
}

// ---------------------------------------------------------------------------
// Implicit-GEMM FFMA conv (3x3 s1 or 4x4 s2, pad 1). Output 64x64 per image.
// Double-buffered smem, register-staged prefetch.
// ---------------------------------------------------------------------------
template<int KSZ, int S>
__global__ __launch_bounds__(256, 2)
void conv_ffma(const float* __restrict__ in, const float* __restrict__ wt,
               const float* __restrict__ bias, float* __restrict__ out,
               int Cin, int Hin, int Win, int Cout, int relu)
{
    __shared__ float sA[2][16*128];
    __shared__ float sB[2][16*128];
    const int tid = threadIdx.x;
    const int tx = tid & 15;
    const int ty = tid >> 4;
    const int m0  = blockIdx.x << 7;
    const int co0 = blockIdx.y << 7;
    const int b   = m0 >> 12;
    const int y0  = (m0 & 4095) >> 6;
    const int cpt = Cin >> 4;
    const int NCH = KSZ*KSZ*cpt;

    float acc[8][8];
#pragma unroll
    for (int i = 0; i < 8; i++)
#pragma unroll
        for (int j = 0; j < 8; j++) acc[i][j] = 0.f;

    float ra[8], rb[8];

    auto loadc = [&](int q) {
        int tap = q / cpt;
        int ci0 = (q - tap*cpt) << 4;
        int dy = tap/KSZ - 1, dx = tap%KSZ - 1;
#pragma unroll
        for (int v = 0; v < 8; v++) {
            int idx = tid + v*256;
            int ci = idx >> 7, pix = idx & 127;
            int iy = (y0 + (pix >> 6))*S + dy;
            int ix = (pix & 63)*S + dx;
            float val = 0.f;
            if ((unsigned)iy < (unsigned)Hin && (unsigned)ix < (unsigned)Win)
                val = in[((size_t)(b*Cin + ci0 + ci)*Hin + iy)*Win + ix];
            ra[v] = val;
            rb[v] = wt[((size_t)tap*Cin + ci0 + ci)*Cout + co0 + pix];
        }
    };
    auto storec = [&](int buf) {
#pragma unroll
        for (int v = 0; v < 8; v++) {
            int idx = tid + v*256;
            int ci = idx >> 7, pix = idx & 127;
            sA[buf][ci*128 + pix] = ra[v];
            sB[buf][ci*128 + pix] = rb[v];
        }
    };

    loadc(0); storec(0); __syncthreads();
    for (int q = 0; q < NCH; q++) {
        if (q + 1 < NCH) loadc(q + 1);
        const float* pA = sA[q & 1];
        const float* pB = sB[q & 1];
#pragma unroll
        for (int kk = 0; kk < 16; kk++) {
            float4 a0 = *(const float4*)&pA[kk*128 + tx*8];
            float4 a1 = *(const float4*)&pA[kk*128 + tx*8 + 4];
            float4 b0 = *(const float4*)&pB[kk*128 + ty*8];
            float4 b1 = *(const float4*)&pB[kk*128 + ty*8 + 4];
            float av[8] = {a0.x,a0.y,a0.z,a0.w,a1.x,a1.y,a1.z,a1.w};
            float bv[8] = {b0.x,b0.y,b0.z,b0.w,b1.x,b1.y,b1.z,b1.w};
#pragma unroll
            for (int i = 0; i < 8; i++)
#pragma unroll
                for (int j = 0; j < 8; j++) acc[i][j] += av[i]*bv[j];
        }
        __syncthreads();
        if (q + 1 < NCH) storec((q + 1) & 1);
        __syncthreads();
    }

    const int yr = y0 + (tx >> 3);
    const int xc = (tx*8) & 63;
#pragma unroll
    for (int j = 0; j < 8; j++) {
        int co = co0 + ty*8 + j;
        float bv = bias[co];
        float4 v0, v1;
        v0.x = acc[0][j]+bv; v0.y = acc[1][j]+bv; v0.z = acc[2][j]+bv; v0.w = acc[3][j]+bv;
        v1.x = acc[4][j]+bv; v1.y = acc[5][j]+bv; v1.z = acc[6][j]+bv; v1.w = acc[7][j]+bv;
        if (relu) {
            v0.x = fmaxf(v0.x,0.f); v0.y = fmaxf(v0.y,0.f); v0.z = fmaxf(v0.z,0.f); v0.w = fmaxf(v0.w,0.f);
            v1.x = fmaxf(v1.x,0.f); v1.y = fmaxf(v1.y,0.f); v1.z = fmaxf(v1.z,0.f); v1.w = fmaxf(v1.w,0.f);
        }
        float* p = out + ((size_t)(b*Cout + co)*4096 + yr*64 + xc);
        *(float4*)p = v0;
        *(float4*)(p + 4) = v1;
    }
}

// ---------------------------------------------------------------------------
// Implicit-GEMM FFMA convT (k4 s2 p1), parity-decomposed, Cout=64, relu.
// Double-buffered smem, register-staged prefetch.
// ---------------------------------------------------------------------------
__global__ __launch_bounds__(256, 2)
void convT_ffma(const float* __restrict__ in, const float* __restrict__ wtT,
                const float* __restrict__ bias, float* __restrict__ out,
                int Cin, int Hin, int Win, int wsh, int hwsh)
{
    __shared__ float sA[2][16*256];
    __shared__ float sB[2][16*64];
    const int tid = threadIdx.x;
    const int tx = tid & 31;
    const int ty = tid >> 5;
    const int P0 = blockIdx.x << 8;
    const int b   = P0 >> hwsh;
    const int lp  = P0 & ((1 << hwsh) - 1);
    const int my0 = lp >> wsh;
    const int p  = blockIdx.z;
    const int ey = p >> 1, ex = p & 1;
    const float* wtp = wtT + (size_t)p*4*Cin*64;
    const int Wo  = Win*2;
    const int HWo = (Hin*Win)*4;
    const int cpt = Cin >> 4;
    const int NCH = 4*cpt;

    float acc[8][8];
#pragma unroll
    for (int i = 0; i < 8; i++)
#pragma unroll
        for (int j = 0; j < 8; j++) acc[i][j] = 0.f;

    float ra[16], rb[4];

    auto loadc = [&](int q) {
        int t = q / cpt;
        int ci0 = (q - t*cpt) << 4;
        int jy = t >> 1, jx = t & 1;
        int ry = (ey == 0) ? (jy == 0 ? 0 : -1) : (jy == 0 ? 1 : 0);
        int rx = (ex == 0) ? (jx == 0 ? 0 : -1) : (jx == 0 ? 1 : 0);
#pragma unroll
        for (int v = 0; v < 16; v++) {
            int idx = tid + v*256;
            int ci = idx >> 8, pix = idx & 255;
            int iy = my0 + (pix >> wsh) + ry;
            int ix = (pix & (Win-1)) + rx;
            float val = 0.f;
            if ((unsigned)iy < (unsigned)Hin && (unsigned)ix < (unsigned)Win)
                val = in[((size_t)(b*Cin + ci0 + ci)*Hin + iy)*Win + ix];
            ra[v] = val;
        }
#pragma unroll
        for (int v = 0; v < 4; v++) {
            int idx = tid + v*256;
            int ci = idx >> 6, n = idx & 63;
            rb[v] = wtp[((size_t)t*Cin + ci0 + ci)*64 + n];
        }
    };
    auto storec = [&](int buf) {
#pragma unroll
        for (int v = 0; v < 16; v++) {
            int idx = tid + v*256;
            int ci = idx >> 8, pix = idx & 255;
            sA[buf][ci*256 + pix] = ra[v];
        }
#pragma unroll
        for (int v = 0; v < 4; v++) {
            int idx = tid + v*256;
            int ci = idx >> 6, n = idx & 63;
            sB[buf][ci*64 + n] = rb[v];
        }
    };

    loadc(0); storec(0); __syncthreads();
    for (int q = 0; q < NCH; q++) {
        if (q + 1 < NCH) loadc(q + 1);
        const float* pA = sA[q & 1];
        const float* pB = sB[q & 1];
#pragma unroll
        for (int kk = 0; kk < 16; kk++) {
            float4 a0 = *(const float4*)&pA[kk*256 + tx*8];
            float4 a1 = *(const float4*)&pA[kk*256 + tx*8 + 4];
            float4 b0 = *(const float4*)&pB[kk*64 + ty*8];
            float4 b1 = *(const float4*)&pB[kk*64 + ty*8 + 4];
            float av[8] = {a0.x,a0.y,a0.z,a0.w,a1.x,a1.y,a1.z,a1.w};
            float bv[8] = {b0.x,b0.y,b0.z,b0.w,b1.x,b1.y,b1.z,b1.w};
#pragma unroll
            for (int i = 0; i < 8; i++)
#pragma unroll
                for (int j = 0; j < 8; j++) acc[i][j] += av[i]*bv[j];
        }
        __syncthreads();
        if (q + 1 < NCH) storec((q + 1) & 1);
        __syncthreads();
    }

    const int m  = my0 + ((tx*8) >> wsh);
    const int oy = 2*m + ey;
#pragma unroll
    for (int j = 0; j < 8; j++) {
        int co = ty*8 + j;
        float bv = bias[co];
        float* p0 = out + ((size_t)(b*64 + co)*HWo + oy*Wo + ex);
#pragma unroll
        for (int i = 0; i < 8; i++) {
            int mx = (tx*8 + i) & (Win-1);
            p0[2*mx] = fmaxf(acc[i][j] + bv, 0.f);
        }
    }
}

// ---------------------------------------------------------------------------
// convT4 (k4 s2 p1, Cin=64 -> Cout=3, tanh): N=12 GEMM (4 parities x 3 couts),
// A-tile (3 rows x 258 cols per ci) shared across parities via 9-tap padding.
// Block = one input row (256 m-px) of one image; thread = 1 m-px, 12 outputs.
// Weights repacked wp[tau(9)][ci(64)][12 pad 16]. Dynamic smem 59904 B.
// ---------------------------------------------------------------------------
__global__ __launch_bounds__(256)
void convT4_ffma(const float* __restrict__ in, const float* __restrict__ wp,
                 const float* __restrict__ bias, float* __restrict__ out)
{
    extern __shared__ float dynf[];
    float* sA = dynf;              // [16 ci][3 rows][264]
    float* sB = dynf + 16*792;     // [9 tau][16 ci][16]

    const int tid = threadIdx.x;
    const int b  = blockIdx.x >> 8;
    const int my = blockIdx.x & 255;
    const float* inb = in + (size_t)b*64*65536;

    float acc[12];
#pragma unroll
    for (int i = 0; i < 12; i++) acc[i] = 0.f;

    for (int ci0 = 0; ci0 < 64; ci0 += 16) {
        for (int idx = tid; idx < 16*3*258; idx += 256) {
            int ci = idx / 774;
            int rem = idx - ci*774;
            int r = rem / 258, c = rem - r*258;
            int iy = my - 1 + r, ix = c - 1;
            float v = 0.f;
            if ((unsigned)iy < 256u && (unsigned)ix < 256u)
                v = inb[((size_t)(ci0 + ci)*256 + iy)*256 + ix];
            sA[ci*792 + r*264 + c] = v;
        }
        for (int idx = tid; idx < 9*16*16; idx += 256) {
            int tau = idx >> 8;
            int rem = idx & 255;
            int ci = rem >> 4, s = rem & 15;
            sB[(tau*16 + ci)*16 + s] = wp[((size_t)tau*64 + ci0 + ci)*16 + s];
        }
        __syncthreads();

        for (int ci = 0; ci < 16; ci++) {
#pragma unroll
            for (int tau = 0; tau < 9; tau++) {
                float a = sA[ci*792 + (tau/3)*264 + (tau%3) + tid];
                const float4* bp = (const float4*)&sB[(tau*16 + ci)*16];
                float4 b0 = bp[0], b1 = bp[1], b2 = bp[2];
                acc[0] += a*b0.x; acc[1]  += a*b0.y; acc[2]  += a*b0.z;
                acc[3] += a*b0.w; acc[4]  += a*b1.x; acc[5]  += a*b1.y;
                acc[6] += a*b1.z; acc[7]  += a*b1.w; acc[8]  += a*b2.x;
                acc[9] += a*b2.y; acc[10] += a*b2.z; acc[11] += a*b2.w;
            }
        }
        __syncthreads();
    }

    const int mx = tid;
#pragma unroll
    for (int p = 0; p < 4; p++) {
        int ey = p >> 1, ex = p & 1;
        int oy = 2*my + ey;
#pragma unroll
        for (int co = 0; co < 3; co++) {
            float v = tanhf(acc[p*3 + co] + bias[co]);
            out[(((size_t)b*3 + co)*512 + oy)*512 + 2*mx + ex] = v;
        }
    }
}

// ---------------------------------------------------------------------------
// Weight repacks
// ---------------------------------------------------------------------------
__global__ void repack_conv_w(const float* __restrict__ w, float* __restrict__ wt,
                              int Cin, int Cout, int KK)
{
    int idx = blockIdx.x*256 + threadIdx.x;
    int total = Cin*Cout*KK;
    if (idx >= total) return;
    int co = idx % Cout; int r = idx / Cout;
    int ci = r % Cin;    int tap = r / Cin;
    wt[idx] = w[(co*Cin + ci)*KK + tap];
}

__global__ void repack_convT_w(const float* __restrict__ w, float* __restrict__ wtT,
                               int Cin, int Cout)
{
    int idx = blockIdx.x*256 + threadIdx.x;
    int total = 16*Cin*Cout;
    if (idx >= total) return;
    int co = idx % Cout; int r = idx / Cout;
    int ci = r % Cin;    int pt = r / Cin;
    int p = pt >> 2, t = pt & 3;
    int ey = p >> 1, ex = p & 1;
    int jy = t >> 1, jx = t & 1;
    int ky = (ey == 0) ? (jy == 0 ? 1 : 3) : (jy == 0 ? 0 : 2);
    int kx = (ex == 0) ? (jx == 0 ? 1 : 3) : (jx == 0 ? 0 : 2);
    wtT[idx] = w[((ci*Cout + co)*4 + ky)*4 + kx];
}

// dec_w4 (ci=64, co=3, 4, 4) -> wp[tau(dy,dx)][ci][s=p*3+co, pad 16]
__global__ void repack_w4n(const float* __restrict__ w, float* __restrict__ wp)
{
    int idx = blockIdx.x*256 + threadIdx.x;
    if (idx >= 9*64*16) return;
    int tau = idx >> 10;
    int rem = idx & 1023;
    int ci = rem >> 4, s = rem & 15;
    float v = 0.f;
    if (s < 12) {
        int p = s / 3, co = s - p*3;
        int ey = p >> 1, ex = p & 1;
        int dy = tau/3 - 1, dx = tau%3 - 1;
        int ky = -1, kx = -1;
        if (ey == 0) { if (dy == 0) ky = 1; else if (dy == -1) ky = 3; }
        else         { if (dy == 1) ky = 0; else if (dy ==  0) ky = 2; }
        if (ex == 0) { if (dx == 0) kx = 1; else if (dx == -1) kx = 3; }
        else         { if (dx == 1) kx = 0; else if (dx ==  0) kx = 2; }
        if (ky >= 0 && kx >= 0)
            v = w[((ci*3 + co)*4 + ky)*4 + kx];
    }
    wp[idx] = v;
}

// ---------------------------------------------------------------------------
// Direct conv (FFMA) — enc1 only (Cin=3).
// ---------------------------------------------------------------------------
template<int K, int S, int CIN_T>
__global__ __launch_bounds__(128)
void conv2d_tiled(const float* __restrict__ in, const float* __restrict__ w,
                  const float* __restrict__ bias, float* __restrict__ out,
                  int Cin, int H, int W, int Cout, int Ho, int Wo,
                  int pad, int relu)
{
    constexpr int IH = 3*S + K;
    constexpr int IW = 15*S + K;
    constexpr int KK = K*K;
    __shared__ __align__(16) float s_in[CIN_T*IH*IW];
    __shared__ __align__(16) float s_w [CIN_T*KK*64];

    const int tid = threadIdx.x;
    const int px  = tid & 15;
    const int cg  = tid >> 4;
    const int hb  = Ho >> 2;
    const int b   = blockIdx.y / hb;
    const int oy0 = (blockIdx.y % hb) * 4;
    const int ox0 = blockIdx.x * 16;
    const int co0 = blockIdx.z * 64;
    const int iy0 = oy0*S - pad;
    const int ix0 = ox0*S - pad;

    float acc[4][8];
#pragma unroll
    for (int p = 0; p < 4; p++)
#pragma unroll
        for (int c = 0; c < 8; c++) acc[p][c] = 0.f;

    for (int ci0 = 0; ci0 < Cin; ci0 += CIN_T) {
        for (int idx = tid; idx < CIN_T*IH*IW; idx += 128) {
            int ci  = idx / (IH*IW);
            int rem = idx % (IH*IW);
            int r   = rem / IW, c = rem % IW;
            int iy  = iy0 + r, ix = ix0 + c;
            float v = 0.f;
            if ((unsigned)iy < (unsigned)H && (unsigned)ix < (unsigned)W &&
                (ci0 + ci) < Cin)
                v = in[((b*Cin + ci0 + ci)*H + iy)*W + ix];
            s_in[idx] = v;
        }
        for (int idx = tid; idx < CIN_T*KK*64; idx += 128) {
            int co  = idx & 63;
            int rem = idx >> 6;
            int kk  = rem % KK;
            int ci  = rem / KK;
            float v = 0.f;
            if ((ci0 + ci) < Cin)
                v = w[((co0 + co)*Cin + ci0 + ci)*KK + kk];
            s_w[idx] = v;
        }
        __syncthreads();

        for (int ci = 0; ci < CIN_T; ci++) {
#pragma unroll
            for (int kh = 0; kh < K; kh++) {
#pragma unroll
                for (int kw = 0; kw < K; kw++) {
                    const float4* wp =
                        (const float4*)(s_w + ((ci*KK + kh*K + kw) << 6) + (cg << 3));
                    float4 w0 = wp[0], w1 = wp[1];
#pragma unroll
                    for (int p = 0; p < 4; p++) {
                        float iv = s_in[(ci*IH + p*S + kh)*IW + px*S + kw];
                        acc[p][0] += iv*w0.x; acc[p][1] += iv*w0.y;
                        acc[p][2] += iv*w0.z; acc[p][3] += iv*w0.w;
                        acc[p][4] += iv*w1.x; acc[p][5] += iv*w1.y;
                        acc[p][6] += iv*w1.z; acc[p][7] += iv*w1.w;
                    }
                }
            }
        }
        __syncthreads();
    }

#pragma unroll
    for (int c = 0; c < 8; c++) {
        int co = co0 + (cg << 3) + c;
        float bv = bias[co];
#pragma unroll
        for (int p = 0; p < 4; p++) {
            float v = acc[p][c] + bv;
            if (relu) v = fmaxf(v, 0.f);
            out[((b*Cout + co)*Ho + oy0 + p)*Wo + ox0 + px] = v;
        }
    }
}

// ---------------------------------------------------------------------------
// Helpers
// ---------------------------------------------------------------------------
__global__ void cnorm_kernel(const float* __restrict__ cb, float* __restrict__ cn) {
    int row  = (blockIdx.x*blockDim.x + threadIdx.x) >> 5;
    int lane = threadIdx.x & 31;
    if (row >= 4096) return;
    const float* p = cb + (size_t)row*256;
    float s = 0.f;
    for (int c = lane; c < 256; c += 32) { float v = p[c]; s += v*v; }
#pragma unroll
    for (int o = 16; o; o >>= 1) s += __shfl_down_sync(0xffffffffu, s, o);
    if (!lane) cn[row] = s;
}

__global__ void zero_loss(double* l) { if (threadIdx.x < 4) l[threadIdx.x] = 0.0; }

__global__ void write_loss(const double* __restrict__ l, float* __restrict__ o) {
    if (threadIdx.x < 4)
        o[threadIdx.x] = (float)(l[threadIdx.x] * (1.0/(65536.0*256.0)));
}

__global__ void z_to_tokens(const float* __restrict__ z,
                            float* __restrict__ resid, float* __restrict__ qsum)
{
    __shared__ float t[32][33];
    int b  = blockIdx.z;
    int s0 = blockIdx.x*32;
    int c0 = blockIdx.y*32;
    int x  = threadIdx.x;
    for (int y = threadIdx.y; y < 32; y += 8)
        t[y][x] = z[((size_t)b*256 + c0 + y)*4096 + s0 + x];
    __syncthreads();
    for (int y = threadIdx.y; y < 32; y += 8) {
        size_t o = ((size_t)b*4096 + s0 + y)*256 + c0 + x;
        resid[o] = t[x][y];
        qsum[o]  = 0.f;
    }
}

__global__ void tokens_to_z(const float* __restrict__ qsum,
                            float* __restrict__ z1, float* __restrict__ z2)
{
    __shared__ float t[32][33];
    int b  = blockIdx.z;
    int c0 = blockIdx.x*32;
    int s0 = blockIdx.y*32;
    int x  = threadIdx.x;
    for (int y = threadIdx.y; y < 32; y += 8)
        t[y][x] = qsum[((size_t)b*4096 + s0 + y)*256 + c0 + x];
    __syncthreads();
    for (int y = threadIdx.y; y < 32; y += 8) {
        float v = t[x][y];
        size_t o = ((size_t)b*256 + c0 + y)*4096 + s0 + x;
        z1[o] = v; z2[o] = v;
    }
}

// ---------------------------------------------------------------------------
// Launch
// ---------------------------------------------------------------------------
extern "C" void kernel_launch(void* const* d_in, const int* in_sizes, int n_in,
                              void* d_out, int out_size)
{
    const float* x   = (const float*)d_in[0];
    const float* ew1 = (const float*)d_in[1];  const float* eb1 = (const float*)d_in[2];
    const float* ew2 = (const float*)d_in[3];  const float* eb2 = (const float*)d_in[4];
    const float* ew3 = (const float*)d_in[5];  const float* eb3 = (const float*)d_in[6];
    const float* ew4 = (const float*)d_in[7];  const float* eb4 = (const float*)d_in[8];
    const float* cbs = (const float*)d_in[9];
    const float* dw1 = (const float*)d_in[10]; const float* db1 = (const float*)d_in[11];
    const float* dw2 = (const float*)d_in[12]; const float* db2 = (const float*)d_in[13];
    const float* dw3 = (const float*)d_in[14]; const float* db3 = (const float*)d_in[15];
    const float* dw4 = (const float*)d_in[16]; const float* db4 = (const float*)d_in[17];
    float* out = (float*)d_out;

    float *h1, *h2, *h3, *z, *resid, *qsum, *cnorm, *w4p, *wt, *wtT, *d3;
    double* loss; unsigned* rowmin;
    cudaGetSymbolAddress((void**)&h1,    g_h1);
    cudaGetSymbolAddress((void**)&h2,    g_h2);
    cudaGetSymbolAddress((void**)&h3,    g_h3);
    cudaGetSymbolAddress((void**)&z,     g_z);
    cudaGetSymbolAddress((void**)&resid, g_resid);
    cudaGetSymbolAddress((void**)&qsum,  g_qsum);
    cudaGetSymbolAddress((void**)&loss,  g_loss);
    cudaGetSymbolAddress((void**)&cnorm, g_cnorm);
    cudaGetSymbolAddress((void**)&rowmin,g_rowmin);
    cudaGetSymbolAddress((void**)&w4p,   g_w4p);
    cudaGetSymbolAddress((void**)&wt,    g_wt);
    cudaGetSymbolAddress((void**)&wtT,   g_wtT);
    cudaGetSymbolAddress((void**)&d3,    g_d3);

    float* wt_e2  = wt;                               // 16*64*128  = 131072
    float* wt_e3  = wt + 131072;                      // 9*128*256  = 294912
    float* wt_e4  = wt + 131072 + 294912;             // 9*256*256  = 589824
    float* wt_d1  = wt + 131072 + 294912 + 589824;    // 9*256*128  = 294912
    float* wtT_d2 = wtT;                              // 16*128*64  = 131072
    float* wtT_d3 = wtT + 131072;                     // 16*64*64   = 65536

    // output layout: recon | indices | commit_loss | quantized
    float* recO   = out;
    float* idxO   = out + 12582912;
    float* lossO  = idxO + 262144;
    float* quantO = lossO + 4;

    const int PA_SMEM  = 2*PLW*4 + 512;               // 34304
    const int CT4_SMEM = (16*792 + 9*16*16)*4;        // 59904
    cudaFuncSetAttribute(vq_gemm_approx, cudaFuncAttributeMaxDynamicSharedMemorySize, PA_SMEM);
    cudaFuncSetAttribute(convT4_ffma,    cudaFuncAttributeMaxDynamicSharedMemorySize, CT4_SMEM);

    // prep
    repack_w4n    <<<36, 256>>>(dw4, w4p);
    cnorm_kernel  <<<512, 256>>>(cbs, cnorm);
    zero_loss     <<<1, 32>>>(loss);
    repack_conv_w <<<(131072+255)/256, 256>>>(ew2, wt_e2,  64, 128, 16);
    repack_conv_w <<<(294912+255)/256, 256>>>(ew3, wt_e3, 128, 256,  9);
    repack_conv_w <<<(589824+255)/256, 256>>>(ew4, wt_e4, 256, 256,  9);
    repack_conv_w <<<(294912+255)/256, 256>>>(dw1, wt_d1, 256, 128,  9);
    repack_convT_w<<<(131072+255)/256, 256>>>(dw2, wtT_d2, 128, 64);
    repack_convT_w<<<( 65536+255)/256, 256>>>(dw3, wtT_d3,  64, 64);

    // ---- encoder ----
    conv2d_tiled<4,2,4><<<dim3(8, 32*16, 1), 128>>>(x, ew1, eb1, h1, 3, 256, 256, 64, 128, 128, 1, 1);
    conv_ffma<4,2><<<dim3(512, 1), 256>>>(h1, wt_e2, eb2, h2,  64, 128, 128, 128, 1);
    conv_ffma<3,1><<<dim3(512, 2), 256>>>(h2, wt_e3, eb3, h3, 128,  64,  64, 256, 1);
    conv_ffma<3,1><<<dim3(512, 2), 256>>>(h3, wt_e4, eb4, z,  256,  64,  64, 256, 0);

    // ---- residual VQ: single-MMA tf32 approx distances (bf16 D) + exact rescore ----
    z_to_tokens<<<dim3(128, 8, 16), dim3(32, 8)>>>(z, resid, qsum);
    __nv_bfloat16* Dh = (__nv_bfloat16*)d3;
    for (int s = 0; s < 4; s++) {
        init_rowmin     <<<64, 1024>>>(rowmin);
        vq_gemm_approx  <<<dim3(512, 8), 256, PA_SMEM>>>(resid, cbs + (size_t)s*1024*256,
                                                         cnorm + s*1024, Dh, rowmin);
        vq_select_update<<<8192, 256>>>(Dh, cbs + (size_t)s*1024*256, cnorm + s*1024,
                                        rowmin, resid, qsum, idxO, s, loss);
    }
    write_loss <<<1, 32>>>(loss, lossO);
    tokens_to_z<<<dim3(8, 128, 16), dim3(32, 8)>>>(qsum, z, quantO);

    // ---- decoder ----
    conv_ffma<3,1><<<dim3(512, 1), 256>>>(z, wt_d1, db1, h2, 256, 64, 64, 128, 1);
    convT_ffma<<<dim3( 256, 1, 4), 256>>>(h2, wtT_d2, db2, h1, 128,  64,  64, 6, 12);
    convT_ffma<<<dim3(1024, 1, 4), 256>>>(h1, wtT_d3, db3, d3,  64, 128, 128, 7, 14);
    convT4_ffma<<<4096, 256, CT4_SMEM>>>(d3, w4p, db4, recO);
}